// round 2
// baseline (speedup 1.0000x reference)
#include <cuda_runtime.h>

#define B_    32
#define N_    8
#define CIN   3
#define HWD   224
#define PATCH 32
#define S_    49
#define C_    384
#define HM_   512
#define CO_   256
#define NP    (B_*N_*S_)          /* 12544 */
#define KCONV (CIN*PATCH*PATCH)   /* 3072  */
#define NE    (B_*N_*N_)          /* 2048  */

// ---- scratch (static device globals; no allocation) ----
__device__ float g_feats[NP * C_];   // 12544 x 384
__device__ float g_a[NP * HM_];      // 12544 x 512
__device__ float g_g[NP * HM_];      // 12544 x 512
__device__ float g_mask[NE];         // 2048
__device__ float g_W2h[HM_ * 7];     // fused W2 @ heads, pre-scaled by 1/49
__device__ float g_bias7[7];         // b2 @ heads + head biases

// ---- packed fp32x2 FMA (sm_103a; PTX-only instruction) ----
__device__ __forceinline__ unsigned long long ffma2(unsigned long long a,
                                                    unsigned long long b,
                                                    unsigned long long c)
{
    unsigned long long d;
    asm("fma.rn.f32x2 %0, %1, %2, %3;" : "=l"(d) : "l"(a), "l"(b), "l"(c));
    return d;
}

__device__ __forceinline__ float2 unpack2(unsigned long long v)
{
    union { unsigned long long u; float2 f; } cv;
    cv.u = v;
    return cv.f;
}

// ============================================================
// Kernel 1: patch embedding as GEMM (FFMA2)
//   feats[p, c] = sum_k img_patch[p, k] * W_patch[c, k] + b_patch[c]
//   M=12544, N=384, K=3072. Tiles: 64x64x16, 4x4 reg tile, 256 thr.
//   Accumulators packed in pairs along M; B duplicated in smem for splats.
// ============================================================
__global__ void patch_embed_kernel(const float* __restrict__ img,
                                   const float* __restrict__ Wp,
                                   const float* __restrict__ bp)
{
    __shared__ __align__(16) float As[16][68];
    __shared__ __align__(16) float BsD[16][132];   // duplicated (b,b) pairs

    const int tid = threadIdx.x;
    const int bm  = blockIdx.x * 64;
    const int bn  = blockIdx.y * 64;
    const int ty  = tid >> 4;          // 0..15
    const int tx  = tid & 15;          // 0..15
    const int lk  = tid & 15;          // A loader k index
    const int lm  = tid >> 4;          // A loader row base

    // precompute image base offsets for the 4 A rows this thread loads
    long rowbase[4];
#pragma unroll
    for (int i = 0; i < 4; i++) {
        int p  = bm + lm + i * 16;
        int n  = p / 49;
        int s  = p - n * 49;
        int py = s / 7;
        int px = s - py * 7;
        rowbase[i] = ((long)n * CIN * HWD + (long)py * PATCH) * HWD + (long)px * PATCH;
    }

    unsigned long long acc[2][4];
#pragma unroll
    for (int p = 0; p < 2; p++)
#pragma unroll
        for (int j = 0; j < 4; j++) acc[p][j] = 0ULL;

    for (int kc = 0; kc < KCONV; kc += 16) {
        int k   = kc + lk;
        int ci  = k >> 10;
        int rem = k & 1023;
        int y   = rem >> 5;
        int x   = rem & 31;
        long off = (long)ci * HWD * HWD + (long)y * HWD + x;
#pragma unroll
        for (int i = 0; i < 4; i++)
            As[lk][lm + i * 16] = img[rowbase[i] + off];
#pragma unroll
        for (int i = 0; i < 4; i++) {
            float v = Wp[(long)(bn + lm + i * 16) * KCONV + k];
            BsD[lk][2 * (lm + i * 16)]     = v;
            BsD[lk][2 * (lm + i * 16) + 1] = v;
        }
        __syncthreads();
#pragma unroll
        for (int kk = 0; kk < 16; kk++) {
            ulonglong2 aP = *(const ulonglong2*)&As[kk][ty * 4];
            ulonglong2 bA = *(const ulonglong2*)&BsD[kk][tx * 8];
            ulonglong2 bB = *(const ulonglong2*)&BsD[kk][tx * 8 + 4];
            acc[0][0] = ffma2(aP.x, bA.x, acc[0][0]);
            acc[1][0] = ffma2(aP.y, bA.x, acc[1][0]);
            acc[0][1] = ffma2(aP.x, bA.y, acc[0][1]);
            acc[1][1] = ffma2(aP.y, bA.y, acc[1][1]);
            acc[0][2] = ffma2(aP.x, bB.x, acc[0][2]);
            acc[1][2] = ffma2(aP.y, bB.x, acc[1][2]);
            acc[0][3] = ffma2(aP.x, bB.y, acc[0][3]);
            acc[1][3] = ffma2(aP.y, bB.y, acc[1][3]);
        }
        __syncthreads();
    }

#pragma unroll
    for (int p = 0; p < 2; p++) {
        int r0 = bm + ty * 4 + 2 * p;
#pragma unroll
        for (int j = 0; j < 4; j++) {
            int c = bn + tx * 4 + j;
            float2 v = unpack2(acc[p][j]);
            float bias = bp[c];
            g_feats[(long)r0 * C_ + c]       = v.x + bias;
            g_feats[(long)(r0 + 1) * C_ + c] = v.y + bias;
        }
    }
}

// ============================================================
// Kernel 2: a = feats @ W1a, g = feats @ W1b (FFMA2)
//   M=12544, K=384, N=512 each. blockIdx.y: 0..7 -> a tiles, 8..15 -> g
// ============================================================
__global__ void ag_gemm_kernel(const float* __restrict__ W1a,
                               const float* __restrict__ W1b)
{
    __shared__ __align__(16) float As[16][68];
    __shared__ __align__(16) float BsD[16][132];

    const int tid = threadIdx.x;
    const int bm  = blockIdx.x * 64;
    const int nt  = blockIdx.y;
    const float* W1;
    float* out;
    int bn;
    if (nt < 8) { W1 = W1a; out = g_a; bn = nt * 64; }
    else        { W1 = W1b; out = g_g; bn = (nt - 8) * 64; }

    const int ty = tid >> 4, tx = tid & 15;
    const int lk = tid & 15, lm = tid >> 4;   // A loader
    const int kb = tid >> 6, cb = tid & 63;   // B loader

    unsigned long long acc[2][4];
#pragma unroll
    for (int p = 0; p < 2; p++)
#pragma unroll
        for (int j = 0; j < 4; j++) acc[p][j] = 0ULL;

    for (int kc = 0; kc < C_; kc += 16) {
#pragma unroll
        for (int i = 0; i < 4; i++)
            As[lk][lm + i * 16] = g_feats[(long)(bm + lm + i * 16) * C_ + kc + lk];
#pragma unroll
        for (int i = 0; i < 4; i++) {
            float v = W1[(long)(kc + kb + i * 4) * HM_ + bn + cb];
            BsD[kb + i * 4][2 * cb]     = v;
            BsD[kb + i * 4][2 * cb + 1] = v;
        }
        __syncthreads();
#pragma unroll
        for (int kk = 0; kk < 16; kk++) {
            ulonglong2 aP = *(const ulonglong2*)&As[kk][ty * 4];
            ulonglong2 bA = *(const ulonglong2*)&BsD[kk][tx * 8];
            ulonglong2 bB = *(const ulonglong2*)&BsD[kk][tx * 8 + 4];
            acc[0][0] = ffma2(aP.x, bA.x, acc[0][0]);
            acc[1][0] = ffma2(aP.y, bA.x, acc[1][0]);
            acc[0][1] = ffma2(aP.x, bA.y, acc[0][1]);
            acc[1][1] = ffma2(aP.y, bA.y, acc[1][1]);
            acc[0][2] = ffma2(aP.x, bB.x, acc[0][2]);
            acc[1][2] = ffma2(aP.y, bB.x, acc[1][2]);
            acc[0][3] = ffma2(aP.x, bB.y, acc[0][3]);
            acc[1][3] = ffma2(aP.y, bB.y, acc[1][3]);
        }
        __syncthreads();
    }

#pragma unroll
    for (int p = 0; p < 2; p++) {
        int r0 = bm + ty * 4 + 2 * p;
#pragma unroll
        for (int j = 0; j < 4; j++) {
            float2 v = unpack2(acc[p][j]);
            out[(long)r0 * HM_ + bn + tx * 4 + j]       = v.x;
            out[(long)(r0 + 1) * HM_ + bn + tx * 4 + j] = v.y;
        }
    }
}

// ============================================================
// Kernel 3: communication mask
// ============================================================
__global__ void mask_kernel(const float* __restrict__ pos, float* __restrict__ out)
{
    int e = blockIdx.x * blockDim.x + threadIdx.x;
    if (e >= NE) return;
    int b = e >> 6;
    int i = (e >> 3) & 7;
    int j = e & 7;
    float xi = pos[(b * N_ + i) * 3 + 0], yi = pos[(b * N_ + i) * 3 + 1];
    float xj = pos[(b * N_ + j) * 3 + 0], yj = pos[(b * N_ + j) * 3 + 1];
    float dx = xi - xj, dy = yi - yj;
    float d2 = __fadd_rn(__fmul_rn(dx, dx), __fmul_rn(dy, dy));
    float m = (d2 < 0.25f && i != j) ? 1.0f : 0.0f;
    g_mask[e] = m;
    out[NE * 7 + e] = m;
}

// ============================================================
// Kernel 4: fold W2 and the 4 head matrices + biases.
//   g_W2h[h,k]  = (1/49) * sum_o W2[h,o] * Whead[o,k]
//   g_bias7[k]  = sum_o b2[o] * Whead[o,k] + bhead[k]
//   Whead cols: [Wp0 Wp1 Wpv0 Wpv1 Wr0 Wr1 Wrv]
// ============================================================
__device__ __forceinline__ float head_w(int o, int k,
                                        const float* Wph, const float* Wpv,
                                        const float* Wr, const float* Wrv)
{
    if (k < 2) return Wph[o * 2 + k];
    if (k < 4) return Wpv[o * 2 + (k - 2)];
    if (k < 6) return Wr[o * 2 + (k - 4)];
    return Wrv[o];
}

__global__ void w2h_kernel(const float* __restrict__ W2, const float* __restrict__ b2,
                           const float* __restrict__ Wph, const float* __restrict__ bph,
                           const float* __restrict__ Wpv, const float* __restrict__ bpv,
                           const float* __restrict__ Wr,  const float* __restrict__ br,
                           const float* __restrict__ Wrv, const float* __restrict__ brv)
{
    int idx = blockIdx.x * blockDim.x + threadIdx.x;
    if (idx < HM_ * 7) {
        int h = idx / 7, k = idx - h * 7;
        float sum = 0.f;
        for (int o = 0; o < CO_; o++)
            sum = fmaf(W2[h * CO_ + o], head_w(o, k, Wph, Wpv, Wr, Wrv), sum);
        g_W2h[idx] = sum * (1.0f / 49.0f);
    } else if (idx < HM_ * 7 + 7) {
        int k = idx - HM_ * 7;
        float sum = 0.f;
        for (int o = 0; o < CO_; o++)
            sum = fmaf(b2[o], head_w(o, k, Wph, Wpv, Wr, Wrv), sum);
        float bb = (k < 2) ? bph[k] : (k < 4) ? bpv[k - 2] : (k < 6) ? br[k - 4] : brv[0];
        g_bias7[k] = sum + bb;
    }
}

// ============================================================
// Kernel 5: edge kernel (restructured).
//   hsum[h] = sum_s relu(a[i,s,h] + g[j,s,h] + b1[h])
//   out7[k] = sum_h hsum[h] * g_W2h[h,k] + g_bias7[k]   (masked: 0)
//   One block per edge; 256 threads; thread covers h = tid and tid+256.
// ============================================================
__global__ void __launch_bounds__(256, 8)
edge_kernel(const float* __restrict__ b1, float* __restrict__ out)
{
    __shared__ float red[7][8];

    const int e   = blockIdx.x;
    const int tid = threadIdx.x;

    float mf = g_mask[e];
    if (mf == 0.0f) {
        if (tid < 7) out[e * 7 + tid] = 0.0f;
        return;
    }

    const int b = e >> 6, i = (e >> 3) & 7, j = e & 7;
    const float* __restrict__ ap = g_a + (long)((b * 8 + i) * 49) * HM_;
    const float* __restrict__ gp = g_g + (long)((b * 8 + j) * 49) * HM_;

    const int h0 = tid, h1 = tid + 256;
    const float base0 = b1[h0], base1 = b1[h1];

    float hs0 = 0.f, hs1 = 0.f;
#pragma unroll 7
    for (int s = 0; s < 49; s++) {
        float v0 = ap[s * HM_ + h0] + gp[s * HM_ + h0] + base0;
        float v1 = ap[s * HM_ + h1] + gp[s * HM_ + h1] + base1;
        hs0 += fmaxf(v0, 0.f);
        hs1 += fmaxf(v1, 0.f);
    }

    float o7[7];
#pragma unroll
    for (int k = 0; k < 7; k++)
        o7[k] = fmaf(hs0, g_W2h[h0 * 7 + k], hs1 * g_W2h[h1 * 7 + k]);

#pragma unroll
    for (int k = 0; k < 7; k++) {
        float v = o7[k];
#pragma unroll
        for (int off = 16; off; off >>= 1)
            v += __shfl_down_sync(0xffffffffu, v, off);
        if ((tid & 31) == 0) red[k][tid >> 5] = v;
    }
    __syncthreads();
    if (tid < 7) {
        float v = 0.f;
#pragma unroll
        for (int w = 0; w < 8; w++) v += red[tid][w];
        out[e * 7 + tid] = v + g_bias7[tid];
    }
}

// ============================================================
// Kernel 6: zero-fill node_preds section
// ============================================================
__global__ void zero_kernel(float* __restrict__ out, int n0, int n1)
{
    int idx = n0 + blockIdx.x * blockDim.x + threadIdx.x;
    if (idx < n1) out[idx] = 0.0f;
}

// ============================================================
extern "C" void kernel_launch(void* const* d_in, const int* in_sizes, int n_in,
                              void* d_out, int out_size)
{
    const float* img    = (const float*)d_in[0];
    const float* pos    = (const float*)d_in[1];
    /* d_in[2] = rot, unused */
    const float* Wpatch = (const float*)d_in[3];
    const float* bpatch = (const float*)d_in[4];
    const float* W1a    = (const float*)d_in[5];
    const float* W1b    = (const float*)d_in[6];
    const float* b1     = (const float*)d_in[7];
    const float* W2     = (const float*)d_in[8];
    const float* b2     = (const float*)d_in[9];
    const float* Wp     = (const float*)d_in[10];
    const float* bp     = (const float*)d_in[11];
    const float* Wpv    = (const float*)d_in[12];
    const float* bpv    = (const float*)d_in[13];
    const float* Wr     = (const float*)d_in[14];
    const float* br     = (const float*)d_in[15];
    const float* Wrv    = (const float*)d_in[16];
    const float* brv    = (const float*)d_in[17];
    float* out = (float*)d_out;

    // independent small work first
    mask_kernel<<<(NE + 255) / 256, 256>>>(pos, out);
    w2h_kernel<<<(HM_ * 7 + 7 + 255) / 256, 256>>>(W2, b2, Wp, bp, Wpv, bpv,
                                                   Wr, br, Wrv, brv);
    // 1) patch embedding (feats)
    patch_embed_kernel<<<dim3(NP / 64, C_ / 64), 256>>>(img, Wpatch, bpatch);
    // 2) a / g projections
    ag_gemm_kernel<<<dim3(NP / 64, 16), 256>>>(W1a, W1b);
    // 3) fused edge MLP + heads
    edge_kernel<<<NE, 256>>>(b1, out);
    // 4) node_preds zeros
    int n0 = NE * 7 + NE;
    int n1 = out_size;
    int cnt = n1 - n0;
    if (cnt > 0)
        zero_kernel<<<(cnt + 255) / 256, 256>>>(out, n0, n1);
}

// round 3
// speedup vs baseline: 2.8590x; 2.8590x over previous
#include <cuda_runtime.h>

#define B_    32
#define N_    8
#define CIN   3
#define HWD   224
#define PATCH 32
#define S_    49
#define C_    384
#define HM_   512
#define CO_   256
#define NP    (B_*N_*S_)          /* 12544 */
#define KCONV (CIN*PATCH*PATCH)   /* 3072  */
#define NE    (B_*N_*N_)          /* 2048  */

// ---- scratch (static device globals; no allocation) ----
__device__ float g_feats[NP * C_];   // 12544 x 384
__device__ float g_a[NP * HM_];      // 12544 x 512
__device__ float g_g[NP * HM_];      // 12544 x 512
__device__ float g_mask[NE];         // 2048
__device__ float g_W2h[HM_ * 7];     // fused W2 @ heads, pre-scaled by 1/49
__device__ float g_bias7[7];         // b2 @ heads + head biases

typedef unsigned long long u64;

// ---- packed fp32x2 FMA (sm_103a; PTX-only) ----
__device__ __forceinline__ u64 ffma2(u64 a, u64 b, u64 c)
{
    u64 d;
    asm("fma.rn.f32x2 %0, %1, %2, %3;" : "=l"(d) : "l"(a), "l"(b), "l"(c));
    return d;
}
__device__ __forceinline__ u64 splat2(float a)
{
    u64 d;
    asm("mov.b64 %0, {%1, %1};" : "=l"(d) : "f"(a));
    return d;
}
__device__ __forceinline__ float2 unpack2(u64 v)
{
    union { u64 u; float2 f; } cv; cv.u = v; return cv.f;
}

// ============================================================
// Kernel 1: patch embedding as GEMM (FFMA2, 128x128x16, 8x8/thread)
//   feats[p, c] = sum_k img_patch[p, k] * Wp[c, k] + bp[c]
//   M=12544, N=384, K=3072
// ============================================================
__global__ void __launch_bounds__(256, 2)
patch_embed_kernel(const float* __restrict__ img,
                   const float* __restrict__ Wp,
                   const float* __restrict__ bp)
{
    __shared__ __align__(16) float As[16][132];
    __shared__ __align__(16) float Bs[16][136];

    const int tid = threadIdx.x;
    const int bm  = blockIdx.x * 128;
    const int bn  = blockIdx.y * 128;
    const int ty  = tid >> 4;          // 0..15 -> row group
    const int tx  = tid & 15;          // 0..15 -> col group
    const int lk  = tid & 15;          // loader k
    const int lr0 = (tid >> 4) * 8;    // loader row/col base (8 elems)

    // per-thread loop-invariant image row bases (fits in int)
    int rowbase[8];
#pragma unroll
    for (int i = 0; i < 8; i++) {
        int p  = bm + lr0 + i;
        int n  = p / 49;
        int s  = p - n * 49;
        int py = s / 7;
        int px = s - py * 7;
        rowbase[i] = (n * CIN * HWD + py * PATCH) * HWD + px * PATCH;
    }

    u64 acc[8][4];
#pragma unroll
    for (int m = 0; m < 8; m++)
#pragma unroll
        for (int n = 0; n < 4; n++) acc[m][n] = 0ULL;

    for (int kc = 0; kc < KCONV; kc += 16) {
        int k   = kc + lk;
        int ci  = k >> 10;
        int rem = k & 1023;
        int off = ci * HWD * HWD + (rem >> 5) * HWD + (rem & 31);
#pragma unroll
        for (int i = 0; i < 8; i++)
            As[lk][lr0 + i] = img[rowbase[i] + off];
#pragma unroll
        for (int i = 0; i < 8; i++)
            Bs[lk][lr0 + i] = Wp[(long)(bn + lr0 + i) * KCONV + k];
        __syncthreads();
#pragma unroll
        for (int kk = 0; kk < 16; kk++) {
            ulonglong2 bP0 = *(const ulonglong2*)&Bs[kk][tx * 8];
            ulonglong2 bP1 = *(const ulonglong2*)&Bs[kk][tx * 8 + 4];
            float4 a0 = *(const float4*)&As[kk][ty * 8];
            float4 a1 = *(const float4*)&As[kk][ty * 8 + 4];
            float av[8] = {a0.x, a0.y, a0.z, a0.w, a1.x, a1.y, a1.z, a1.w};
#pragma unroll
            for (int m = 0; m < 8; m++) {
                u64 as = splat2(av[m]);
                acc[m][0] = ffma2(as, bP0.x, acc[m][0]);
                acc[m][1] = ffma2(as, bP0.y, acc[m][1]);
                acc[m][2] = ffma2(as, bP1.x, acc[m][2]);
                acc[m][3] = ffma2(as, bP1.y, acc[m][3]);
            }
        }
        __syncthreads();
    }

#pragma unroll
    for (int m = 0; m < 8; m++) {
        int r = bm + ty * 8 + m;
#pragma unroll
        for (int n = 0; n < 4; n++) {
            int c = bn + tx * 8 + n * 2;
            float2 v = unpack2(acc[m][n]);
            v.x += bp[c];
            v.y += bp[c + 1];
            *(float2*)&g_feats[(long)r * C_ + c] = v;
        }
    }
}

// ============================================================
// Kernel 2: a = feats @ W1a, g = feats @ W1b (FFMA2, 128x128x16)
//   M=12544, K=384, N=512 each. blockIdx.y: 0..3 -> a, 4..7 -> g
// ============================================================
__global__ void __launch_bounds__(256, 2)
ag_gemm_kernel(const float* __restrict__ W1a,
               const float* __restrict__ W1b)
{
    __shared__ __align__(16) float As[16][132];
    __shared__ __align__(16) float Bs[16][136];

    const int tid = threadIdx.x;
    const int bm  = blockIdx.x * 128;
    const int nt  = blockIdx.y;
    const float* W1;
    float* out;
    int bn;
    if (nt < 4) { W1 = W1a; out = g_a; bn = nt * 128; }
    else        { W1 = W1b; out = g_g; bn = (nt - 4) * 128; }

    const int ty  = tid >> 4, tx = tid & 15;
    const int lk  = tid & 15;          // A loader k
    const int lr0 = (tid >> 4) * 8;    // A loader row base
    const int kB  = tid >> 4;          // B loader k (0..15)
    const int nq  = (tid & 15) * 8;    // B loader col base

    int rowbase[8];
#pragma unroll
    for (int i = 0; i < 8; i++)
        rowbase[i] = (bm + lr0 + i) * C_;

    u64 acc[8][4];
#pragma unroll
    for (int m = 0; m < 8; m++)
#pragma unroll
        for (int n = 0; n < 4; n++) acc[m][n] = 0ULL;

    for (int kc = 0; kc < C_; kc += 16) {
#pragma unroll
        for (int i = 0; i < 8; i++)
            As[lk][lr0 + i] = g_feats[rowbase[i] + kc + lk];
        {
            const float* wrow = W1 + (long)(kc + kB) * HM_ + bn + nq;
            float4 w0 = *(const float4*)wrow;
            float4 w1 = *(const float4*)(wrow + 4);
            *(float4*)&Bs[kB][nq]     = w0;
            *(float4*)&Bs[kB][nq + 4] = w1;
        }
        __syncthreads();
#pragma unroll
        for (int kk = 0; kk < 16; kk++) {
            ulonglong2 bP0 = *(const ulonglong2*)&Bs[kk][tx * 8];
            ulonglong2 bP1 = *(const ulonglong2*)&Bs[kk][tx * 8 + 4];
            float4 a0 = *(const float4*)&As[kk][ty * 8];
            float4 a1 = *(const float4*)&As[kk][ty * 8 + 4];
            float av[8] = {a0.x, a0.y, a0.z, a0.w, a1.x, a1.y, a1.z, a1.w};
#pragma unroll
            for (int m = 0; m < 8; m++) {
                u64 as = splat2(av[m]);
                acc[m][0] = ffma2(as, bP0.x, acc[m][0]);
                acc[m][1] = ffma2(as, bP0.y, acc[m][1]);
                acc[m][2] = ffma2(as, bP1.x, acc[m][2]);
                acc[m][3] = ffma2(as, bP1.y, acc[m][3]);
            }
        }
        __syncthreads();
    }

#pragma unroll
    for (int m = 0; m < 8; m++) {
        int r = bm + ty * 8 + m;
#pragma unroll
        for (int n = 0; n < 4; n++) {
            float2 v = unpack2(acc[m][n]);
            *(float2*)&out[(long)r * HM_ + bn + tx * 8 + n * 2] = v;
        }
    }
}

// ============================================================
// Kernel 3: communication mask
// ============================================================
__global__ void mask_kernel(const float* __restrict__ pos, float* __restrict__ out)
{
    int e = blockIdx.x * blockDim.x + threadIdx.x;
    if (e >= NE) return;
    int b = e >> 6;
    int i = (e >> 3) & 7;
    int j = e & 7;
    float xi = pos[(b * N_ + i) * 3 + 0], yi = pos[(b * N_ + i) * 3 + 1];
    float xj = pos[(b * N_ + j) * 3 + 0], yj = pos[(b * N_ + j) * 3 + 1];
    float dx = xi - xj, dy = yi - yj;
    float d2 = __fadd_rn(__fmul_rn(dx, dx), __fmul_rn(dy, dy));
    float m = (d2 < 0.25f && i != j) ? 1.0f : 0.0f;
    g_mask[e] = m;
    out[NE * 7 + e] = m;
}

// ============================================================
// Kernel 4: fold W2 and the 4 head matrices + biases.
// ============================================================
__device__ __forceinline__ float head_w(int o, int k,
                                        const float* Wph, const float* Wpv,
                                        const float* Wr, const float* Wrv)
{
    if (k < 2) return Wph[o * 2 + k];
    if (k < 4) return Wpv[o * 2 + (k - 2)];
    if (k < 6) return Wr[o * 2 + (k - 4)];
    return Wrv[o];
}

__global__ void w2h_kernel(const float* __restrict__ W2, const float* __restrict__ b2,
                           const float* __restrict__ Wph, const float* __restrict__ bph,
                           const float* __restrict__ Wpv, const float* __restrict__ bpv,
                           const float* __restrict__ Wr,  const float* __restrict__ br,
                           const float* __restrict__ Wrv, const float* __restrict__ brv)
{
    int idx = blockIdx.x * blockDim.x + threadIdx.x;
    if (idx < HM_ * 7) {
        int h = idx / 7, k = idx - h * 7;
        float sum = 0.f;
        for (int o = 0; o < CO_; o++)
            sum = fmaf(W2[h * CO_ + o], head_w(o, k, Wph, Wpv, Wr, Wrv), sum);
        g_W2h[idx] = sum * (1.0f / 49.0f);
    } else if (idx < HM_ * 7 + 7) {
        int k = idx - HM_ * 7;
        float sum = 0.f;
        for (int o = 0; o < CO_; o++)
            sum = fmaf(b2[o], head_w(o, k, Wph, Wpv, Wr, Wrv), sum);
        float bb = (k < 2) ? bph[k] : (k < 4) ? bpv[k - 2] : (k < 6) ? br[k - 4] : brv[0];
        g_bias7[k] = sum + bb;
    }
}

// ============================================================
// Kernel 5: edge kernel (algebraic collapse over s first).
//   hsum[h] = sum_s relu(a[i,s,h] + g[j,s,h] + b1[h])
//   out7[k] = sum_h hsum[h] * g_W2h[h,k] + g_bias7[k]
// ============================================================
__global__ void __launch_bounds__(256, 8)
edge_kernel(const float* __restrict__ b1, float* __restrict__ out)
{
    __shared__ float red[7][8];

    const int e   = blockIdx.x;
    const int tid = threadIdx.x;

    float mf = g_mask[e];
    if (mf == 0.0f) {
        if (tid < 7) out[e * 7 + tid] = 0.0f;
        return;
    }

    const int b = e >> 6, i = (e >> 3) & 7, j = e & 7;
    const float* __restrict__ ap = g_a + (long)((b * 8 + i) * 49) * HM_;
    const float* __restrict__ gp = g_g + (long)((b * 8 + j) * 49) * HM_;

    const int h0 = tid, h1 = tid + 256;
    const float base0 = b1[h0], base1 = b1[h1];

    float hs0 = 0.f, hs1 = 0.f;
#pragma unroll 7
    for (int s = 0; s < 49; s++) {
        float v0 = ap[s * HM_ + h0] + gp[s * HM_ + h0] + base0;
        float v1 = ap[s * HM_ + h1] + gp[s * HM_ + h1] + base1;
        hs0 += fmaxf(v0, 0.f);
        hs1 += fmaxf(v1, 0.f);
    }

    float o7[7];
#pragma unroll
    for (int k = 0; k < 7; k++)
        o7[k] = fmaf(hs0, g_W2h[h0 * 7 + k], hs1 * g_W2h[h1 * 7 + k]);

#pragma unroll
    for (int k = 0; k < 7; k++) {
        float v = o7[k];
#pragma unroll
        for (int off = 16; off; off >>= 1)
            v += __shfl_down_sync(0xffffffffu, v, off);
        if ((tid & 31) == 0) red[k][tid >> 5] = v;
    }
    __syncthreads();
    if (tid < 7) {
        float v = 0.f;
#pragma unroll
        for (int w = 0; w < 8; w++) v += red[tid][w];
        out[e * 7 + tid] = v + g_bias7[tid];
    }
}

// ============================================================
// Kernel 6: zero-fill node_preds section
// ============================================================
__global__ void zero_kernel(float* __restrict__ out, int n0, int n1)
{
    int idx = n0 + blockIdx.x * blockDim.x + threadIdx.x;
    if (idx < n1) out[idx] = 0.0f;
}

// ============================================================
extern "C" void kernel_launch(void* const* d_in, const int* in_sizes, int n_in,
                              void* d_out, int out_size)
{
    const float* img    = (const float*)d_in[0];
    const float* pos    = (const float*)d_in[1];
    /* d_in[2] = rot, unused */
    const float* Wpatch = (const float*)d_in[3];
    const float* bpatch = (const float*)d_in[4];
    const float* W1a    = (const float*)d_in[5];
    const float* W1b    = (const float*)d_in[6];
    const float* b1     = (const float*)d_in[7];
    const float* W2     = (const float*)d_in[8];
    const float* b2     = (const float*)d_in[9];
    const float* Wp     = (const float*)d_in[10];
    const float* bp     = (const float*)d_in[11];
    const float* Wpv    = (const float*)d_in[12];
    const float* bpv    = (const float*)d_in[13];
    const float* Wr     = (const float*)d_in[14];
    const float* br     = (const float*)d_in[15];
    const float* Wrv    = (const float*)d_in[16];
    const float* brv    = (const float*)d_in[17];
    float* out = (float*)d_out;

    // independent small work first
    mask_kernel<<<(NE + 255) / 256, 256>>>(pos, out);
    w2h_kernel<<<(HM_ * 7 + 7 + 255) / 256, 256>>>(W2, b2, Wp, bp, Wpv, bpv,
                                                   Wr, br, Wrv, brv);
    // 1) patch embedding (feats): grid 98 x 3
    patch_embed_kernel<<<dim3(NP / 128, C_ / 128), 256>>>(img, Wpatch, bpatch);
    // 2) a / g projections: grid 98 x 8
    ag_gemm_kernel<<<dim3(NP / 128, 8), 256>>>(W1a, W1b);
    // 3) fused edge MLP + heads
    edge_kernel<<<NE, 256>>>(b1, out);
    // 4) node_preds zeros
    int n0 = NE * 7 + NE;
    int n1 = out_size;
    int cnt = n1 - n0;
    if (cnt > 0)
        zero_kernel<<<(cnt + 255) / 256, 256>>>(out, n0, n1);
}

// round 5
// speedup vs baseline: 5.1034x; 1.7850x over previous
#include <cuda_runtime.h>
#include <cuda_bf16.h>
#include <cstdint>

#define B_    32
#define N_    8
#define CIN   3
#define HWD   224
#define PATCH 32
#define S_    49
#define C_    384
#define HM_   512
#define CO_   256
#define NP    12544
#define KCONV 3072
#define NE    2048
#define NAG   1024

// ---- scratch (static device globals; no allocation) ----
__device__ __align__(16) __nv_bfloat16 g_Wph[C_ * KCONV];
__device__ __align__(16) __nv_bfloat16 g_Wpl[C_ * KCONV];
__device__ __align__(16) __nv_bfloat16 g_W1t_h[NAG * C_];
__device__ __align__(16) __nv_bfloat16 g_W1t_l[NAG * C_];
__device__ __align__(16) __nv_bfloat16 g_feats_h[NP * C_];
__device__ __align__(16) __nv_bfloat16 g_feats_l[NP * C_];
__device__ float g_a[NP * HM_];
__device__ float g_g[NP * HM_];
__device__ float g_mask[NE];
__device__ float g_W2h[HM_ * 7];
__device__ float g_bias7[7];

// ---- helpers ----
__device__ __forceinline__ uint32_t smem_to_u32(const void* p) {
    uint32_t a;
    asm("{ .reg .u64 t; cvta.to.shared.u64 t, %1; cvt.u32.u64 %0, t; }" : "=r"(a) : "l"(p));
    return a;
}
__device__ __forceinline__ void cp16(uint32_t dst, const void* src) {
    asm volatile("cp.async.cg.shared.global [%0], [%1], 16;" :: "r"(dst), "l"(src));
}
#define CP_COMMIT() asm volatile("cp.async.commit_group;" ::: "memory")
#define CP_WAIT1()  asm volatile("cp.async.wait_group 1;" ::: "memory")
#define CP_WAIT0()  asm volatile("cp.async.wait_group 0;" ::: "memory")

__device__ __forceinline__ void ldm4(uint32_t* r, uint32_t addr) {
    asm volatile("ldmatrix.sync.aligned.m8n8.x4.shared.b16 {%0,%1,%2,%3}, [%4];"
                 : "=r"(r[0]), "=r"(r[1]), "=r"(r[2]), "=r"(r[3]) : "r"(addr));
}
__device__ __forceinline__ void mma16816(float* c, const uint32_t* a,
                                         uint32_t b0, uint32_t b1) {
    asm volatile(
        "mma.sync.aligned.m16n8k16.row.col.f32.bf16.bf16.f32 "
        "{%0,%1,%2,%3}, {%4,%5,%6,%7}, {%8,%9}, {%0,%1,%2,%3};"
        : "+f"(c[0]), "+f"(c[1]), "+f"(c[2]), "+f"(c[3])
        : "r"(a[0]), "r"(a[1]), "r"(a[2]), "r"(a[3]), "r"(b0), "r"(b1));
}

__device__ __forceinline__ void bsplit(float x, __nv_bfloat16& h, __nv_bfloat16& l) {
    h = __float2bfloat16(x);
    l = __float2bfloat16(x - __bfloat162float(h));
}
__device__ __forceinline__ uint32_t pk2(__nv_bfloat16 a, __nv_bfloat16 b) {
    __nv_bfloat162 t(a, b);
    return *reinterpret_cast<uint32_t*>(&t);
}

// smem stage layout: rows of 32 bf16 padded to 80B (conflict-free mod 128)
#define ROWB   80
#define TILE_B (128 * ROWB)            /* 10240 */
#define STAGE_B (4 * TILE_B)           /* Ah Al Bh Bl = 40960 */
#define SMEM_BYTES (2 * STAGE_B)       /* 81920 */
#define OFF_AH 0
#define OFF_AL TILE_B
#define OFF_BH (2 * TILE_B)
#define OFF_BL (3 * TILE_B)

// ---- shared GEMM core: one K=32 chunk (two k16 steps), 3-pass bf16 ----
__device__ __forceinline__ void gemm_chunk(uint32_t sbase, int wm, int wn, int lane,
                                           float acc[4][4][4])
{
#pragma unroll
    for (int step = 0; step < 2; step++) {
        const uint32_t co = (uint32_t)(step * 32 + (lane >> 4) * 16);
        uint32_t afh[4][4], afl[4][4], bfh[2][4], bfl[2][4];
#pragma unroll
        for (int mi = 0; mi < 4; mi++) {
            uint32_t ro = (uint32_t)((wm * 64 + mi * 16 + (lane & 15)) * ROWB) + co;
            ldm4(afh[mi], sbase + OFF_AH + ro);
            ldm4(afl[mi], sbase + OFF_AL + ro);
        }
#pragma unroll
        for (int nj = 0; nj < 2; nj++) {
            uint32_t ro = (uint32_t)((wn * 32 + nj * 16 + (lane & 15)) * ROWB) + co;
            ldm4(bfh[nj], sbase + OFF_BH + ro);
            ldm4(bfl[nj], sbase + OFF_BL + ro);
        }
#pragma unroll
        for (int mi = 0; mi < 4; mi++)
#pragma unroll
            for (int ni = 0; ni < 4; ni++) {
                int nj = ni >> 1, o = ni & 1;
                mma16816(acc[mi][ni], afh[mi], bfh[nj][o], bfh[nj][o + 2]);
                mma16816(acc[mi][ni], afh[mi], bfl[nj][o], bfl[nj][o + 2]);
                mma16816(acc[mi][ni], afl[mi], bfh[nj][o], bfh[nj][o + 2]);
            }
    }
}

// ============================================================
// Prep kernels
// ============================================================
__global__ void wp_prep(const float* __restrict__ Wp)
{
    int i4 = blockIdx.x * blockDim.x + threadIdx.x;
    if (i4 >= C_ * KCONV / 4) return;
    float4 v = *(const float4*)&Wp[i4 * 4];
    __nv_bfloat16 h0, h1, h2, h3, l0, l1, l2, l3;
    bsplit(v.x, h0, l0); bsplit(v.y, h1, l1); bsplit(v.z, h2, l2); bsplit(v.w, h3, l3);
    *(uint2*)&g_Wph[i4 * 4] = make_uint2(pk2(h0, h1), pk2(h2, h3));
    *(uint2*)&g_Wpl[i4 * 4] = make_uint2(pk2(l0, l1), pk2(l2, l3));
}

__global__ void w1_prep(const float* __restrict__ W1a, const float* __restrict__ W1b)
{
    int idx = blockIdx.x * blockDim.x + threadIdx.x;
    if (idx >= NAG * C_) return;
    int n = idx / C_, k = idx - n * C_;
    float v = (n < HM_) ? W1a[k * HM_ + n] : W1b[k * HM_ + (n - HM_)];
    __nv_bfloat16 h, l;
    bsplit(v, h, l);
    g_W1t_h[idx] = h;
    g_W1t_l[idx] = l;
}

// ============================================================
// Patch GEMM: feats[12544 x 384] = im2row(img) x Wp^T, HMMA 3-pass
// grid (98, 3), 256 thr, 80KB dyn smem, K=3072 (96 chunks of 32)
// ============================================================
__global__ void __launch_bounds__(256, 1)
patch_mma_kernel(const float* __restrict__ img, const float* __restrict__ bp)
{
    extern __shared__ __align__(128) char smem[];
    const uint32_t sb = smem_to_u32(smem);
    const int tid = threadIdx.x, lane = tid & 31, w = tid >> 5;
    const int wm = w >> 2, wn = w & 3;
    const int bm = blockIdx.x * 128, bn = blockIdx.y * 128;

    // A loader: row = tid/2, half = tid&1 (16 contiguous floats)
    const int lrow = tid >> 1, lhalf = tid & 1;
    const float* abase;
    {
        int p  = bm + lrow;
        int n  = p / 49;
        int s  = p - n * 49;
        int py = s / 7, px = s - py * 7;
        abase = img + (n * CIN * HWD + py * PATCH) * HWD + px * PATCH + lhalf * 16;
    }

    float acc[4][4][4];
#pragma unroll
    for (int mi = 0; mi < 4; mi++)
#pragma unroll
        for (int ni = 0; ni < 4; ni++)
#pragma unroll
            for (int t = 0; t < 4; t++) acc[mi][ni][t] = 0.f;

    float4 areg[4];

    auto ldA = [&](int c) {
        int k = c * 32, ci = k >> 10, rem = k & 1023, y = rem >> 5;
        const float4* src = (const float4*)(abase + ci * (HWD * HWD) + y * HWD);
        areg[0] = src[0]; areg[1] = src[1]; areg[2] = src[2]; areg[3] = src[3];
    };
    auto stA = [&](int st) {
        char* dh = smem + st * STAGE_B + OFF_AH + lrow * ROWB + lhalf * 32;
        float v[16] = {areg[0].x, areg[0].y, areg[0].z, areg[0].w,
                       areg[1].x, areg[1].y, areg[1].z, areg[1].w,
                       areg[2].x, areg[2].y, areg[2].z, areg[2].w,
                       areg[3].x, areg[3].y, areg[3].z, areg[3].w};
        uint32_t hp[8], lp[8];
#pragma unroll
        for (int t = 0; t < 8; t++) {
            __nv_bfloat16 h0, l0, h1, l1;
            bsplit(v[2 * t], h0, l0);
            bsplit(v[2 * t + 1], h1, l1);
            hp[t] = pk2(h0, h1);
            lp[t] = pk2(l0, l1);
        }
        *(uint4*)dh               = make_uint4(hp[0], hp[1], hp[2], hp[3]);
        *(uint4*)(dh + 16)        = make_uint4(hp[4], hp[5], hp[6], hp[7]);
        *(uint4*)(dh + TILE_B)      = make_uint4(lp[0], lp[1], lp[2], lp[3]);
        *(uint4*)(dh + TILE_B + 16) = make_uint4(lp[4], lp[5], lp[6], lp[7]);
    };
    auto cpB = [&](int c, int st) {
        int kc = c * 32;
#pragma unroll
        for (int u = 0; u < 2; u++) {
            int idx = tid + u * 256;
            int row = idx >> 2, q = idx & 3;
            uint32_t dst = sb + st * STAGE_B + OFF_BH + row * ROWB + q * 16;
            long so = (long)(bn + row) * KCONV + kc + q * 8;
            cp16(dst, &g_Wph[so]);
            cp16(dst + TILE_B, &g_Wpl[so]);
        }
    };

    ldA(0);
    cpB(0, 0); CP_COMMIT();

    const int NC = KCONV / 32;   // 96
#pragma unroll 1
    for (int c = 0; c < NC; c++) {
        int s = c & 1;
        stA(s);
        bool more = (c + 1 < NC);
        if (more) { cpB(c + 1, s ^ 1); CP_COMMIT(); CP_WAIT1(); }
        else      { CP_WAIT0(); }
        __syncthreads();
        if (more) ldA(c + 1);
        gemm_chunk(sb + s * STAGE_B, wm, wn, lane, acc);
        __syncthreads();
    }

    // epilogue: + bias, split to bf16 h/l feats
    const int r  = lane >> 2;
    const int cc = (lane & 3) * 2;
#pragma unroll
    for (int mi = 0; mi < 4; mi++) {
#pragma unroll
        for (int ni = 0; ni < 4; ni++) {
            int m0  = bm + wm * 64 + mi * 16 + r;
            int col = bn + wn * 32 + ni * 8 + cc;
            float b0 = bp[col], b1 = bp[col + 1];
            {
                float x0 = acc[mi][ni][0] + b0, x1 = acc[mi][ni][1] + b1;
                __nv_bfloat16 h0, l0, h1, l1;
                bsplit(x0, h0, l0); bsplit(x1, h1, l1);
                *(uint32_t*)&g_feats_h[(long)m0 * C_ + col] = pk2(h0, h1);
                *(uint32_t*)&g_feats_l[(long)m0 * C_ + col] = pk2(l0, l1);
            }
            {
                float x0 = acc[mi][ni][2] + b0, x1 = acc[mi][ni][3] + b1;
                __nv_bfloat16 h0, l0, h1, l1;
                bsplit(x0, h0, l0); bsplit(x1, h1, l1);
                *(uint32_t*)&g_feats_h[(long)(m0 + 8) * C_ + col] = pk2(h0, h1);
                *(uint32_t*)&g_feats_l[(long)(m0 + 8) * C_ + col] = pk2(l0, l1);
            }
        }
    }
}

// ============================================================
// a|g GEMM: [12544 x 1024] = feats x W1t^T, HMMA 3-pass
// grid (98, 8), K=384 (12 chunks of 32)
// ============================================================
__global__ void __launch_bounds__(256, 1)
ag_mma_kernel()
{
    extern __shared__ __align__(128) char smem[];
    const uint32_t sb = smem_to_u32(smem);
    const int tid = threadIdx.x, lane = tid & 31, w = tid >> 5;
    const int wm = w >> 2, wn = w & 3;
    const int bm = blockIdx.x * 128, bn = blockIdx.y * 128;

    float acc[4][4][4];
#pragma unroll
    for (int mi = 0; mi < 4; mi++)
#pragma unroll
        for (int ni = 0; ni < 4; ni++)
#pragma unroll
            for (int t = 0; t < 4; t++) acc[mi][ni][t] = 0.f;

    auto cpAB = [&](int c, int st) {
        int kc = c * 32;
#pragma unroll
        for (int u = 0; u < 2; u++) {
            int idx = tid + u * 256;
            int row = idx >> 2, q = idx & 3;
            uint32_t base = sb + st * STAGE_B + row * ROWB + q * 16;
            long ao = (long)(bm + row) * C_ + kc + q * 8;
            long bo = (long)(bn + row) * C_ + kc + q * 8;
            cp16(base + OFF_AH, &g_feats_h[ao]);
            cp16(base + OFF_AL, &g_feats_l[ao]);
            cp16(base + OFF_BH, &g_W1t_h[bo]);
            cp16(base + OFF_BL, &g_W1t_l[bo]);
        }
    };

    cpAB(0, 0); CP_COMMIT();

    const int NC = C_ / 32;   // 12
#pragma unroll 1
    for (int c = 0; c < NC; c++) {
        int s = c & 1;
        bool more = (c + 1 < NC);
        if (more) { cpAB(c + 1, s ^ 1); CP_COMMIT(); CP_WAIT1(); }
        else      { CP_WAIT0(); }
        __syncthreads();
        gemm_chunk(sb + s * STAGE_B, wm, wn, lane, acc);
        __syncthreads();
    }

    float* dst = (bn < HM_) ? g_a : g_g;
    const int nb = (bn < HM_) ? bn : bn - HM_;
    const int r  = lane >> 2;
    const int cc = (lane & 3) * 2;
#pragma unroll
    for (int mi = 0; mi < 4; mi++) {
#pragma unroll
        for (int ni = 0; ni < 4; ni++) {
            int m0  = bm + wm * 64 + mi * 16 + r;
            int col = nb + wn * 32 + ni * 8 + cc;
            *(float2*)&dst[(long)m0 * HM_ + col] =
                make_float2(acc[mi][ni][0], acc[mi][ni][1]);
            *(float2*)&dst[(long)(m0 + 8) * HM_ + col] =
                make_float2(acc[mi][ni][2], acc[mi][ni][3]);
        }
    }
}

// ============================================================
// mask / head-fold / edge / zero
// ============================================================
__global__ void mask_kernel(const float* __restrict__ pos, float* __restrict__ out)
{
    int e = blockIdx.x * blockDim.x + threadIdx.x;
    if (e >= NE) return;
    int b = e >> 6, i = (e >> 3) & 7, j = e & 7;
    float xi = pos[(b * N_ + i) * 3 + 0], yi = pos[(b * N_ + i) * 3 + 1];
    float xj = pos[(b * N_ + j) * 3 + 0], yj = pos[(b * N_ + j) * 3 + 1];
    float dx = xi - xj, dy = yi - yj;
    float d2 = __fadd_rn(__fmul_rn(dx, dx), __fmul_rn(dy, dy));
    float m = (d2 < 0.25f && i != j) ? 1.0f : 0.0f;
    g_mask[e] = m;
    out[NE * 7 + e] = m;
}

__device__ __forceinline__ float head_w(int o, int k,
                                        const float* Wph, const float* Wpv,
                                        const float* Wr, const float* Wrv)
{
    if (k < 2) return Wph[o * 2 + k];
    if (k < 4) return Wpv[o * 2 + (k - 2)];
    if (k < 6) return Wr[o * 2 + (k - 4)];
    return Wrv[o];
}

__global__ void w2h_kernel(const float* __restrict__ W2, const float* __restrict__ b2,
                           const float* __restrict__ Wph, const float* __restrict__ bph,
                           const float* __restrict__ Wpv, const float* __restrict__ bpv,
                           const float* __restrict__ Wr,  const float* __restrict__ br,
                           const float* __restrict__ Wrv, const float* __restrict__ brv)
{
    int idx = blockIdx.x * blockDim.x + threadIdx.x;
    if (idx < HM_ * 7) {
        int h = idx / 7, k = idx - h * 7;
        float sum = 0.f;
        for (int o = 0; o < CO_; o++)
            sum = fmaf(W2[h * CO_ + o], head_w(o, k, Wph, Wpv, Wr, Wrv), sum);
        g_W2h[idx] = sum * (1.0f / 49.0f);
    } else if (idx < HM_ * 7 + 7) {
        int k = idx - HM_ * 7;
        float sum = 0.f;
        for (int o = 0; o < CO_; o++)
            sum = fmaf(b2[o], head_w(o, k, Wph, Wpv, Wr, Wrv), sum);
        float bb = (k < 2) ? bph[k] : (k < 4) ? bpv[k - 2] : (k < 6) ? br[k - 4] : brv[0];
        g_bias7[k] = sum + bb;
    }
}

__global__ void __launch_bounds__(256, 8)
edge_kernel(const float* __restrict__ b1, float* __restrict__ out)
{
    __shared__ float red[7][8];

    const int e   = blockIdx.x;
    const int tid = threadIdx.x;

    float mf = g_mask[e];
    if (mf == 0.0f) {
        if (tid < 7) out[e * 7 + tid] = 0.0f;
        return;
    }

    const int b = e >> 6, i = (e >> 3) & 7, j = e & 7;
    const float* __restrict__ ap = g_a + (long)((b * 8 + i) * 49) * HM_;
    const float* __restrict__ gp = g_g + (long)((b * 8 + j) * 49) * HM_;

    const int h0 = tid, h1 = tid + 256;
    const float base0 = b1[h0], base1 = b1[h1];

    float hs0 = 0.f, hs1 = 0.f;
#pragma unroll 7
    for (int s = 0; s < 49; s++) {
        float v0 = ap[s * HM_ + h0] + gp[s * HM_ + h0] + base0;
        float v1 = ap[s * HM_ + h1] + gp[s * HM_ + h1] + base1;
        hs0 += fmaxf(v0, 0.f);
        hs1 += fmaxf(v1, 0.f);
    }

    float o7[7];
#pragma unroll
    for (int k = 0; k < 7; k++)
        o7[k] = fmaf(hs0, g_W2h[h0 * 7 + k], hs1 * g_W2h[h1 * 7 + k]);

#pragma unroll
    for (int k = 0; k < 7; k++) {
        float v = o7[k];
#pragma unroll
        for (int off = 16; off; off >>= 1)
            v += __shfl_down_sync(0xffffffffu, v, off);
        if ((tid & 31) == 0) red[k][tid >> 5] = v;
    }
    __syncthreads();
    if (tid < 7) {
        float v = 0.f;
#pragma unroll
        for (int w = 0; w < 8; w++) v += red[tid][w];
        out[e * 7 + tid] = v + g_bias7[tid];
    }
}

__global__ void zero_kernel(float* __restrict__ out, int n0, int n1)
{
    int idx = n0 + blockIdx.x * blockDim.x + threadIdx.x;
    if (idx < n1) out[idx] = 0.0f;
}

// ============================================================
extern "C" void kernel_launch(void* const* d_in, const int* in_sizes, int n_in,
                              void* d_out, int out_size)
{
    const float* img    = (const float*)d_in[0];
    const float* pos    = (const float*)d_in[1];
    /* d_in[2] = rot, unused */
    const float* Wpatch = (const float*)d_in[3];
    const float* bpatch = (const float*)d_in[4];
    const float* W1a    = (const float*)d_in[5];
    const float* W1b    = (const float*)d_in[6];
    const float* b1     = (const float*)d_in[7];
    const float* W2     = (const float*)d_in[8];
    const float* b2     = (const float*)d_in[9];
    const float* Wp     = (const float*)d_in[10];
    const float* bp     = (const float*)d_in[11];
    const float* Wpv    = (const float*)d_in[12];
    const float* bpv    = (const float*)d_in[13];
    const float* Wr     = (const float*)d_in[14];
    const float* br     = (const float*)d_in[15];
    const float* Wrv    = (const float*)d_in[16];
    const float* brv    = (const float*)d_in[17];
    float* out = (float*)d_out;

    cudaFuncSetAttribute(patch_mma_kernel,
                         cudaFuncAttributeMaxDynamicSharedMemorySize, SMEM_BYTES);
    cudaFuncSetAttribute(ag_mma_kernel,
                         cudaFuncAttributeMaxDynamicSharedMemorySize, SMEM_BYTES);

    // independent prep
    wp_prep<<<(C_ * KCONV / 4 + 255) / 256, 256>>>(Wpatch);
    w1_prep<<<(NAG * C_ + 255) / 256, 256>>>(W1a, W1b);
    mask_kernel<<<(NE + 255) / 256, 256>>>(pos, out);
    w2h_kernel<<<(HM_ * 7 + 7 + 255) / 256, 256>>>(W2, b2, Wp, bp, Wpv, bpv,
                                                   Wr, br, Wrv, brv);
    // patch embedding GEMM (HMMA)
    patch_mma_kernel<<<dim3(NP / 128, C_ / 128), 256, SMEM_BYTES>>>(img, bpatch);
    // a|g GEMM (HMMA)
    ag_mma_kernel<<<dim3(NP / 128, NAG / 128), 256, SMEM_BYTES>>>();
    // fused edge MLP + heads
    edge_kernel<<<NE, 256>>>(b1, out);
    // node_preds zeros
    int n0 = NE * 7 + NE;
    int cnt = out_size - n0;
    if (cnt > 0)
        zero_kernel<<<(cnt + 255) / 256, 256>>>(out, n0, out_size);
}

// round 6
// speedup vs baseline: 5.3275x; 1.0439x over previous
#include <cuda_runtime.h>
#include <cuda_bf16.h>
#include <cstdint>

#define B_    32
#define N_    8
#define CIN   3
#define HWD   224
#define PATCH 32
#define S_    49
#define C_    384
#define HM_   512
#define CO_   256
#define NP    12544
#define KCONV 3072
#define NE    2048
#define NAG   1024

// ---- scratch (static device globals; no allocation) ----
__device__ __align__(16) __nv_bfloat16 g_Wph[C_ * KCONV];
__device__ __align__(16) __nv_bfloat16 g_Wpl[C_ * KCONV];
__device__ __align__(16) __nv_bfloat16 g_W1t_h[NAG * C_];
__device__ __align__(16) __nv_bfloat16 g_W1t_l[NAG * C_];
__device__ __align__(16) __nv_bfloat16 g_feats_h[NP * C_];
__device__ __align__(16) __nv_bfloat16 g_feats_l[NP * C_];
__device__ float g_a[NP * HM_];
__device__ float g_g[NP * HM_];
__device__ float g_mask[NE];
__device__ float g_W2h[HM_ * 7];
__device__ float g_bias7[7];

// ---- helpers ----
__device__ __forceinline__ uint32_t smem_to_u32(const void* p) {
    uint32_t a;
    asm("{ .reg .u64 t; cvta.to.shared.u64 t, %1; cvt.u32.u64 %0, t; }" : "=r"(a) : "l"(p));
    return a;
}
__device__ __forceinline__ void cp16(uint32_t dst, const void* src) {
    asm volatile("cp.async.cg.shared.global [%0], [%1], 16;" :: "r"(dst), "l"(src));
}
#define CP_COMMIT() asm volatile("cp.async.commit_group;" ::: "memory")
#define CP_WAIT1()  asm volatile("cp.async.wait_group 1;" ::: "memory")
#define CP_WAIT0()  asm volatile("cp.async.wait_group 0;" ::: "memory")

__device__ __forceinline__ void ldm4(uint32_t* r, uint32_t addr) {
    asm volatile("ldmatrix.sync.aligned.m8n8.x4.shared.b16 {%0,%1,%2,%3}, [%4];"
                 : "=r"(r[0]), "=r"(r[1]), "=r"(r[2]), "=r"(r[3]) : "r"(addr));
}
__device__ __forceinline__ void mma16816(float* c, const uint32_t* a,
                                         uint32_t b0, uint32_t b1) {
    asm volatile(
        "mma.sync.aligned.m16n8k16.row.col.f32.bf16.bf16.f32 "
        "{%0,%1,%2,%3}, {%4,%5,%6,%7}, {%8,%9}, {%0,%1,%2,%3};"
        : "+f"(c[0]), "+f"(c[1]), "+f"(c[2]), "+f"(c[3])
        : "r"(a[0]), "r"(a[1]), "r"(a[2]), "r"(a[3]), "r"(b0), "r"(b1));
}

__device__ __forceinline__ void bsplit(float x, __nv_bfloat16& h, __nv_bfloat16& l) {
    h = __float2bfloat16(x);
    l = __float2bfloat16(x - __bfloat162float(h));
}
__device__ __forceinline__ uint32_t pk2(__nv_bfloat16 a, __nv_bfloat16 b) {
    __nv_bfloat162 t(a, b);
    return *reinterpret_cast<uint32_t*>(&t);
}

// smem stage layout: rows of 32 bf16 padded to 80B (conflict-free mod 128)
#define ROWB   80
#define TILE_B (128 * ROWB)
#define STAGE_B (4 * TILE_B)
#define SMEM_BYTES (2 * STAGE_B)
#define OFF_AH 0
#define OFF_AL TILE_B
#define OFF_BH (2 * TILE_B)
#define OFF_BL (3 * TILE_B)

// ---- shared GEMM core: one K=32 chunk (two k16 steps), 3-pass bf16 ----
__device__ __forceinline__ void gemm_chunk(uint32_t sbase, int wm, int wn, int lane,
                                           float acc[4][4][4])
{
#pragma unroll
    for (int step = 0; step < 2; step++) {
        const uint32_t co = (uint32_t)(step * 32 + (lane >> 4) * 16);
        uint32_t afh[4][4], afl[4][4], bfh[2][4], bfl[2][4];
#pragma unroll
        for (int mi = 0; mi < 4; mi++) {
            uint32_t ro = (uint32_t)((wm * 64 + mi * 16 + (lane & 15)) * ROWB) + co;
            ldm4(afh[mi], sbase + OFF_AH + ro);
            ldm4(afl[mi], sbase + OFF_AL + ro);
        }
#pragma unroll
        for (int nj = 0; nj < 2; nj++) {
            uint32_t ro = (uint32_t)((wn * 32 + nj * 16 + (lane & 15)) * ROWB) + co;
            ldm4(bfh[nj], sbase + OFF_BH + ro);
            ldm4(bfl[nj], sbase + OFF_BL + ro);
        }
#pragma unroll
        for (int mi = 0; mi < 4; mi++)
#pragma unroll
            for (int ni = 0; ni < 4; ni++) {
                int nj = ni >> 1, o = ni & 1;
                mma16816(acc[mi][ni], afh[mi], bfh[nj][o], bfh[nj][o + 2]);
                mma16816(acc[mi][ni], afh[mi], bfl[nj][o], bfl[nj][o + 2]);
                mma16816(acc[mi][ni], afl[mi], bfh[nj][o], bfh[nj][o + 2]);
            }
    }
}

// ============================================================
// Prep kernels
// ============================================================
__global__ void wp_prep(const float* __restrict__ Wp)
{
    int i4 = blockIdx.x * blockDim.x + threadIdx.x;
    if (i4 >= C_ * KCONV / 4) return;
    float4 v = *(const float4*)&Wp[i4 * 4];
    __nv_bfloat16 h0, h1, h2, h3, l0, l1, l2, l3;
    bsplit(v.x, h0, l0); bsplit(v.y, h1, l1); bsplit(v.z, h2, l2); bsplit(v.w, h3, l3);
    *(uint2*)&g_Wph[i4 * 4] = make_uint2(pk2(h0, h1), pk2(h2, h3));
    *(uint2*)&g_Wpl[i4 * 4] = make_uint2(pk2(l0, l1), pk2(l2, l3));
}

__global__ void w1_prep(const float* __restrict__ W1a, const float* __restrict__ W1b)
{
    int idx = blockIdx.x * blockDim.x + threadIdx.x;
    if (idx >= NAG * C_) return;
    int n = idx / C_, k = idx - n * C_;
    float v = (n < HM_) ? W1a[k * HM_ + n] : W1b[k * HM_ + (n - HM_)];
    __nv_bfloat16 h, l;
    bsplit(v, h, l);
    g_W1t_h[idx] = h;
    g_W1t_l[idx] = l;
}

// ============================================================
// Patch GEMM: feats[12544 x 384] = im2row(img) x Wp^T, HMMA 3-pass
// ============================================================
__global__ void __launch_bounds__(256, 1)
patch_mma_kernel(const float* __restrict__ img, const float* __restrict__ bp)
{
    extern __shared__ __align__(128) char smem[];
    const uint32_t sb = smem_to_u32(smem);
    const int tid = threadIdx.x, lane = tid & 31, w = tid >> 5;
    const int wm = w >> 2, wn = w & 3;
    const int bm = blockIdx.x * 128, bn = blockIdx.y * 128;

    const int lrow = tid >> 1, lhalf = tid & 1;
    const float* abase;
    {
        int p  = bm + lrow;
        int n  = p / 49;
        int s  = p - n * 49;
        int py = s / 7, px = s - py * 7;
        abase = img + (n * CIN * HWD + py * PATCH) * HWD + px * PATCH + lhalf * 16;
    }

    float acc[4][4][4];
#pragma unroll
    for (int mi = 0; mi < 4; mi++)
#pragma unroll
        for (int ni = 0; ni < 4; ni++)
#pragma unroll
            for (int t = 0; t < 4; t++) acc[mi][ni][t] = 0.f;

    float4 areg[4];

    auto ldA = [&](int c) {
        int k = c * 32, ci = k >> 10, rem = k & 1023, y = rem >> 5;
        const float4* src = (const float4*)(abase + ci * (HWD * HWD) + y * HWD);
        areg[0] = src[0]; areg[1] = src[1]; areg[2] = src[2]; areg[3] = src[3];
    };
    auto stA = [&](int st) {
        char* dh = smem + st * STAGE_B + OFF_AH + lrow * ROWB + lhalf * 32;
        float v[16] = {areg[0].x, areg[0].y, areg[0].z, areg[0].w,
                       areg[1].x, areg[1].y, areg[1].z, areg[1].w,
                       areg[2].x, areg[2].y, areg[2].z, areg[2].w,
                       areg[3].x, areg[3].y, areg[3].z, areg[3].w};
        uint32_t hp[8], lp[8];
#pragma unroll
        for (int t = 0; t < 8; t++) {
            __nv_bfloat16 h0, l0, h1, l1;
            bsplit(v[2 * t], h0, l0);
            bsplit(v[2 * t + 1], h1, l1);
            hp[t] = pk2(h0, h1);
            lp[t] = pk2(l0, l1);
        }
        *(uint4*)dh               = make_uint4(hp[0], hp[1], hp[2], hp[3]);
        *(uint4*)(dh + 16)        = make_uint4(hp[4], hp[5], hp[6], hp[7]);
        *(uint4*)(dh + TILE_B)      = make_uint4(lp[0], lp[1], lp[2], lp[3]);
        *(uint4*)(dh + TILE_B + 16) = make_uint4(lp[4], lp[5], lp[6], lp[7]);
    };
    auto cpB = [&](int c, int st) {
        int kc = c * 32;
#pragma unroll
        for (int u = 0; u < 2; u++) {
            int idx = tid + u * 256;
            int row = idx >> 2, q = idx & 3;
            uint32_t dst = sb + st * STAGE_B + OFF_BH + row * ROWB + q * 16;
            long so = (long)(bn + row) * KCONV + kc + q * 8;
            cp16(dst, &g_Wph[so]);
            cp16(dst + TILE_B, &g_Wpl[so]);
        }
    };

    ldA(0);
    cpB(0, 0); CP_COMMIT();

    const int NC = KCONV / 32;
#pragma unroll 1
    for (int c = 0; c < NC; c++) {
        int s = c & 1;
        stA(s);
        bool more = (c + 1 < NC);
        if (more) { cpB(c + 1, s ^ 1); CP_COMMIT(); CP_WAIT1(); }
        else      { CP_WAIT0(); }
        __syncthreads();
        if (more) ldA(c + 1);
        gemm_chunk(sb + s * STAGE_B, wm, wn, lane, acc);
        __syncthreads();
    }

    const int r  = lane >> 2;
    const int cc = (lane & 3) * 2;
#pragma unroll
    for (int mi = 0; mi < 4; mi++) {
#pragma unroll
        for (int ni = 0; ni < 4; ni++) {
            int m0  = bm + wm * 64 + mi * 16 + r;
            int col = bn + wn * 32 + ni * 8 + cc;
            float b0 = bp[col], b1 = bp[col + 1];
            {
                float x0 = acc[mi][ni][0] + b0, x1 = acc[mi][ni][1] + b1;
                __nv_bfloat16 h0, l0, h1, l1;
                bsplit(x0, h0, l0); bsplit(x1, h1, l1);
                *(uint32_t*)&g_feats_h[(long)m0 * C_ + col] = pk2(h0, h1);
                *(uint32_t*)&g_feats_l[(long)m0 * C_ + col] = pk2(l0, l1);
            }
            {
                float x0 = acc[mi][ni][2] + b0, x1 = acc[mi][ni][3] + b1;
                __nv_bfloat16 h0, l0, h1, l1;
                bsplit(x0, h0, l0); bsplit(x1, h1, l1);
                *(uint32_t*)&g_feats_h[(long)(m0 + 8) * C_ + col] = pk2(h0, h1);
                *(uint32_t*)&g_feats_l[(long)(m0 + 8) * C_ + col] = pk2(l0, l1);
            }
        }
    }
}

// ============================================================
// a|g GEMM: [12544 x 1024] = feats x W1t^T, HMMA 3-pass
// ============================================================
__global__ void __launch_bounds__(256, 1)
ag_mma_kernel()
{
    extern __shared__ __align__(128) char smem[];
    const uint32_t sb = smem_to_u32(smem);
    const int tid = threadIdx.x, lane = tid & 31, w = tid >> 5;
    const int wm = w >> 2, wn = w & 3;
    const int bm = blockIdx.x * 128, bn = blockIdx.y * 128;

    float acc[4][4][4];
#pragma unroll
    for (int mi = 0; mi < 4; mi++)
#pragma unroll
        for (int ni = 0; ni < 4; ni++)
#pragma unroll
            for (int t = 0; t < 4; t++) acc[mi][ni][t] = 0.f;

    auto cpAB = [&](int c, int st) {
        int kc = c * 32;
#pragma unroll
        for (int u = 0; u < 2; u++) {
            int idx = tid + u * 256;
            int row = idx >> 2, q = idx & 3;
            uint32_t base = sb + st * STAGE_B + row * ROWB + q * 16;
            long ao = (long)(bm + row) * C_ + kc + q * 8;
            long bo = (long)(bn + row) * C_ + kc + q * 8;
            cp16(base + OFF_AH, &g_feats_h[ao]);
            cp16(base + OFF_AL, &g_feats_l[ao]);
            cp16(base + OFF_BH, &g_W1t_h[bo]);
            cp16(base + OFF_BL, &g_W1t_l[bo]);
        }
    };

    cpAB(0, 0); CP_COMMIT();

    const int NC = C_ / 32;
#pragma unroll 1
    for (int c = 0; c < NC; c++) {
        int s = c & 1;
        bool more = (c + 1 < NC);
        if (more) { cpAB(c + 1, s ^ 1); CP_COMMIT(); CP_WAIT1(); }
        else      { CP_WAIT0(); }
        __syncthreads();
        gemm_chunk(sb + s * STAGE_B, wm, wn, lane, acc);
        __syncthreads();
    }

    float* dst = (bn < HM_) ? g_a : g_g;
    const int nb = (bn < HM_) ? bn : bn - HM_;
    const int r  = lane >> 2;
    const int cc = (lane & 3) * 2;
#pragma unroll
    for (int mi = 0; mi < 4; mi++) {
#pragma unroll
        for (int ni = 0; ni < 4; ni++) {
            int m0  = bm + wm * 64 + mi * 16 + r;
            int col = nb + wn * 32 + ni * 8 + cc;
            *(float2*)&dst[(long)m0 * HM_ + col] =
                make_float2(acc[mi][ni][0], acc[mi][ni][1]);
            *(float2*)&dst[(long)(m0 + 8) * HM_ + col] =
                make_float2(acc[mi][ni][2], acc[mi][ni][3]);
        }
    }
}

// ============================================================
// mask kernel
// ============================================================
__global__ void mask_kernel(const float* __restrict__ pos, float* __restrict__ out)
{
    int e = blockIdx.x * blockDim.x + threadIdx.x;
    if (e >= NE) return;
    int b = e >> 6, i = (e >> 3) & 7, j = e & 7;
    float xi = pos[(b * N_ + i) * 3 + 0], yi = pos[(b * N_ + i) * 3 + 1];
    float xj = pos[(b * N_ + j) * 3 + 0], yj = pos[(b * N_ + j) * 3 + 1];
    float dx = xi - xj, dy = yi - yj;
    float d2 = __fadd_rn(__fmul_rn(dx, dx), __fmul_rn(dy, dy));
    float m = (d2 < 0.25f && i != j) ? 1.0f : 0.0f;
    g_mask[e] = m;
    out[NE * 7 + e] = m;
}

// ============================================================
// w2h kernel (REWRITTEN): warp-per-h-row.
//   grid 64, block 256 (8 warps). Warp w computes g_W2h[h=blk*8+w][0..6].
//   Whead [256 x 7] staged in smem; W2 row read coalesced.
// ============================================================
__device__ __forceinline__ float head_w(int o, int k,
                                        const float* Wph, const float* Wpv,
                                        const float* Wr, const float* Wrv)
{
    if (k < 2) return Wph[o * 2 + k];
    if (k < 4) return Wpv[o * 2 + (k - 2)];
    if (k < 6) return Wr[o * 2 + (k - 4)];
    return Wrv[o];
}

__global__ void __launch_bounds__(256)
w2h_kernel(const float* __restrict__ W2, const float* __restrict__ b2,
           const float* __restrict__ Wph, const float* __restrict__ bph,
           const float* __restrict__ Wpv, const float* __restrict__ bpv,
           const float* __restrict__ Wr,  const float* __restrict__ br,
           const float* __restrict__ Wrv, const float* __restrict__ brv)
{
    __shared__ float sW[CO_][7];
    const int tid = threadIdx.x, lane = tid & 31, wid = tid >> 5;

    if (tid < CO_) {
#pragma unroll
        for (int k = 0; k < 7; k++)
            sW[tid][k] = head_w(tid, k, Wph, Wpv, Wr, Wrv);
    }
    __syncthreads();

    const int h = blockIdx.x * 8 + wid;
    float acc[7] = {0, 0, 0, 0, 0, 0, 0};
#pragma unroll
    for (int t = 0; t < 8; t++) {
        int o = lane + 32 * t;
        float w2 = W2[h * CO_ + o];
#pragma unroll
        for (int k = 0; k < 7; k++)
            acc[k] = fmaf(w2, sW[o][k], acc[k]);
    }
#pragma unroll
    for (int k = 0; k < 7; k++) {
#pragma unroll
        for (int off = 16; off; off >>= 1)
            acc[k] += __shfl_down_sync(0xffffffffu, acc[k], off);
    }
    if (lane == 0) {
#pragma unroll
        for (int k = 0; k < 7; k++)
            g_W2h[h * 7 + k] = acc[k] * (1.0f / 49.0f);
    }

    if (blockIdx.x == 0 && tid < 7) {
        float sum = 0.f;
        for (int o = 0; o < CO_; o++)
            sum = fmaf(b2[o], sW[o][tid], sum);
        float bb = (tid < 2) ? bph[tid] : (tid < 4) ? bpv[tid - 2]
                 : (tid < 6) ? br[tid - 4] : brv[0];
        g_bias7[tid] = sum + bb;
    }
}

// ============================================================
// edge kernel (REWRITTEN): per-(b, i-half) block, thread-per-h.
//   grid 64 = 32 b x 2 i-halves; 512 threads (h = tid).
//   acc[4 i][8 j] hsum registers; a/g each streamed once per block.
// ============================================================
__global__ void __launch_bounds__(512, 1)
edge_b_kernel(const float* __restrict__ b1, float* __restrict__ out)
{
    __shared__ float red[16][28];
    __shared__ float sbias[7];

    const int blk = blockIdx.x;
    const int b   = blk >> 1;
    const int ih  = blk & 1;           // i in [ih*4, ih*4+4)
    const int tid = threadIdx.x, lane = tid & 31, wid = tid >> 5;

    if (tid < 7) sbias[tid] = g_bias7[tid];

    const float base = b1[tid];
    const float* __restrict__ ap = g_a + ((long)(b * 8 + ih * 4) * 49) * HM_ + tid;
    const float* __restrict__ gp = g_g + ((long)(b * 8) * 49) * HM_ + tid;

    float acc[32];
#pragma unroll
    for (int p = 0; p < 32; p++) acc[p] = 0.f;

#pragma unroll 1
    for (int s = 0; s < 49; s++) {
        const int so = s * HM_;
        float av[4], gv[8];
#pragma unroll
        for (int i = 0; i < 4; i++)
            av[i] = ap[i * (49 * HM_) + so] + base;
#pragma unroll
        for (int j = 0; j < 8; j++)
            gv[j] = gp[j * (49 * HM_) + so];
#pragma unroll
        for (int i = 0; i < 4; i++)
#pragma unroll
            for (int j = 0; j < 8; j++)
                acc[i * 8 + j] += fmaxf(av[i] + gv[j], 0.f);
    }

    float w[7];
#pragma unroll
    for (int k = 0; k < 7; k++) w[k] = g_W2h[tid * 7 + k];

    __syncthreads();   // sbias ready; also separates red[] usage

    // reduce 32 pairs x 7 outputs over 512 threads, 4 pairs per round
#pragma unroll 1
    for (int p0 = 0; p0 < 32; p0 += 4) {
        float pr[28];
#pragma unroll
        for (int q = 0; q < 4; q++)
#pragma unroll
            for (int k = 0; k < 7; k++)
                pr[q * 7 + k] = acc[p0 + q] * w[k];
#pragma unroll
        for (int t = 0; t < 28; t++) {
#pragma unroll
            for (int off = 16; off; off >>= 1)
                pr[t] += __shfl_down_sync(0xffffffffu, pr[t], off);
        }
        if (lane == 0) {
#pragma unroll
            for (int t = 0; t < 28; t++) red[wid][t] = pr[t];
        }
        __syncthreads();
        if (tid < 28) {
            float v = 0.f;
#pragma unroll
            for (int ww = 0; ww < 16; ww++) v += red[ww][tid];
            int q = tid / 7, k = tid - 7 * q;
            int p = p0 + q;                       // pair index within this block
            int i = ih * 4 + (p >> 3), j = p & 7;
            int e = b * 64 + i * 8 + j;
            float mf = g_mask[e];
            out[e * 7 + k] = (mf != 0.f) ? (v + sbias[k]) : 0.f;
        }
        __syncthreads();
    }
}

// ============================================================
// zero-fill node_preds section
// ============================================================
__global__ void zero_kernel(float* __restrict__ out, int n0, int n1)
{
    int idx = n0 + blockIdx.x * blockDim.x + threadIdx.x;
    if (idx < n1) out[idx] = 0.0f;
}

// ============================================================
extern "C" void kernel_launch(void* const* d_in, const int* in_sizes, int n_in,
                              void* d_out, int out_size)
{
    const float* img    = (const float*)d_in[0];
    const float* pos    = (const float*)d_in[1];
    /* d_in[2] = rot, unused */
    const float* Wpatch = (const float*)d_in[3];
    const float* bpatch = (const float*)d_in[4];
    const float* W1a    = (const float*)d_in[5];
    const float* W1b    = (const float*)d_in[6];
    const float* b1     = (const float*)d_in[7];
    const float* W2     = (const float*)d_in[8];
    const float* b2     = (const float*)d_in[9];
    const float* Wp     = (const float*)d_in[10];
    const float* bp     = (const float*)d_in[11];
    const float* Wpv    = (const float*)d_in[12];
    const float* bpv    = (const float*)d_in[13];
    const float* Wr     = (const float*)d_in[14];
    const float* br     = (const float*)d_in[15];
    const float* Wrv    = (const float*)d_in[16];
    const float* brv    = (const float*)d_in[17];
    float* out = (float*)d_out;

    cudaFuncSetAttribute(patch_mma_kernel,
                         cudaFuncAttributeMaxDynamicSharedMemorySize, SMEM_BYTES);
    cudaFuncSetAttribute(ag_mma_kernel,
                         cudaFuncAttributeMaxDynamicSharedMemorySize, SMEM_BYTES);

    // independent prep
    wp_prep<<<(C_ * KCONV / 4 + 255) / 256, 256>>>(Wpatch);
    w1_prep<<<(NAG * C_ + 255) / 256, 256>>>(W1a, W1b);
    mask_kernel<<<(NE + 255) / 256, 256>>>(pos, out);
    w2h_kernel<<<64, 256>>>(W2, b2, Wp, bp, Wpv, bpv, Wr, br, Wrv, brv);
    // patch embedding GEMM (HMMA)
    patch_mma_kernel<<<dim3(NP / 128, C_ / 128), 256, SMEM_BYTES>>>(img, bpatch);
    // a|g GEMM (HMMA)
    ag_mma_kernel<<<dim3(NP / 128, NAG / 128), 256, SMEM_BYTES>>>();
    // fused edge MLP + heads (per-b blocks)
    edge_b_kernel<<<64, 512>>>(b1, out);
    // node_preds zeros
    int n0 = NE * 7 + NE;
    int cnt = out_size - n0;
    if (cnt > 0)
        zero_kernel<<<(cnt + 255) / 256, 256>>>(out, n0, out_size);
}

// round 7
// speedup vs baseline: 7.4771x; 1.4035x over previous
#include <cuda_runtime.h>
#include <cuda_bf16.h>
#include <cuda_fp16.h>
#include <cstdint>

#define B_    32
#define N_    8
#define CIN   3
#define HWD   224
#define PATCH 32
#define S_    49
#define C_    384
#define HM_   512
#define CO_   256
#define NP    12544
#define KCONV 3072
#define NE    2048
#define NAG   1024

// ---- scratch (static device globals; no allocation) ----
__device__ __align__(16) __half         g_Wph[C_ * KCONV];      // fp16 hi only
__device__ __align__(16) __nv_bfloat16  g_W1t_h[NAG * C_];
__device__ __align__(16) __nv_bfloat16  g_W1t_l[NAG * C_];
__device__ __align__(16) __nv_bfloat16  g_feats_h[NP * C_];
__device__ __align__(16) __nv_bfloat16  g_feats_l[NP * C_];
__device__ float g_a[NP * HM_];
__device__ float g_g[NP * HM_];
__device__ float g_mask[NE];
__device__ float g_W2h[HM_ * 7];
__device__ float g_bias7[7];

// ---- helpers ----
__device__ __forceinline__ uint32_t smem_to_u32(const void* p) {
    uint32_t a;
    asm("{ .reg .u64 t; cvta.to.shared.u64 t, %1; cvt.u32.u64 %0, t; }" : "=r"(a) : "l"(p));
    return a;
}
__device__ __forceinline__ void cp16(uint32_t dst, const void* src) {
    asm volatile("cp.async.cg.shared.global [%0], [%1], 16;" :: "r"(dst), "l"(src));
}
#define CP_COMMIT() asm volatile("cp.async.commit_group;" ::: "memory")
#define CP_WAIT1()  asm volatile("cp.async.wait_group 1;" ::: "memory")
#define CP_WAIT0()  asm volatile("cp.async.wait_group 0;" ::: "memory")

__device__ __forceinline__ void ldm4(uint32_t* r, uint32_t addr) {
    asm volatile("ldmatrix.sync.aligned.m8n8.x4.shared.b16 {%0,%1,%2,%3}, [%4];"
                 : "=r"(r[0]), "=r"(r[1]), "=r"(r[2]), "=r"(r[3]) : "r"(addr));
}
__device__ __forceinline__ void mma_bf16(float* c, const uint32_t* a,
                                         uint32_t b0, uint32_t b1) {
    asm volatile(
        "mma.sync.aligned.m16n8k16.row.col.f32.bf16.bf16.f32 "
        "{%0,%1,%2,%3}, {%4,%5,%6,%7}, {%8,%9}, {%0,%1,%2,%3};"
        : "+f"(c[0]), "+f"(c[1]), "+f"(c[2]), "+f"(c[3])
        : "r"(a[0]), "r"(a[1]), "r"(a[2]), "r"(a[3]), "r"(b0), "r"(b1));
}
__device__ __forceinline__ void mma_f16(float* c, const uint32_t* a,
                                        uint32_t b0, uint32_t b1) {
    asm volatile(
        "mma.sync.aligned.m16n8k16.row.col.f32.f16.f16.f32 "
        "{%0,%1,%2,%3}, {%4,%5,%6,%7}, {%8,%9}, {%0,%1,%2,%3};"
        : "+f"(c[0]), "+f"(c[1]), "+f"(c[2]), "+f"(c[3])
        : "r"(a[0]), "r"(a[1]), "r"(a[2]), "r"(a[3]), "r"(b0), "r"(b1));
}

__device__ __forceinline__ void bsplit(float x, __nv_bfloat16& h, __nv_bfloat16& l) {
    h = __float2bfloat16(x);
    l = __float2bfloat16(x - __bfloat162float(h));
}
__device__ __forceinline__ uint32_t pk2(__nv_bfloat16 a, __nv_bfloat16 b) {
    __nv_bfloat162 t(a, b);
    return *reinterpret_cast<uint32_t*>(&t);
}
__device__ __forceinline__ void hsplit2(float x, float y, uint32_t& hp, uint32_t& lp) {
    __half hx = __float2half_rn(x), hy = __float2half_rn(y);
    __half lx = __float2half_rn(x - __half2float(hx));
    __half ly = __float2half_rn(y - __half2float(hy));
    __half2 h(hx, hy), l(lx, ly);
    hp = *reinterpret_cast<uint32_t*>(&h);
    lp = *reinterpret_cast<uint32_t*>(&l);
}

// smem rows: 32 x b16 elems (64B data) padded to 80B (conflict-free mod 128)
#define ROWB    80
#define TILE_B  (128 * ROWB)           /* 10240 */
// ag (3-pass bf16): 4 tiles per stage
#define AG_STAGE   (4 * TILE_B)
#define AG_SMEM    (2 * AG_STAGE)      /* 81920 */
#define OFF_AH  0
#define OFF_AL  TILE_B
#define OFF_BH  (2 * TILE_B)
#define OFF_BL  (3 * TILE_B)
// patch (2-pass fp16): 3 tiles per stage
#define P_STAGE    (3 * TILE_B)
#define P_SMEM     (2 * P_STAGE)       /* 61440 */

// ============================================================
// Prep kernels
// ============================================================
__global__ void wp_prep(const float* __restrict__ Wp)
{
    int i4 = blockIdx.x * blockDim.x + threadIdx.x;
    if (i4 >= C_ * KCONV / 4) return;
    float4 v = *(const float4*)&Wp[i4 * 4];
    __half2 a = __floats2half2_rn(v.x, v.y);
    __half2 b = __floats2half2_rn(v.z, v.w);
    *(uint2*)&g_Wph[i4 * 4] = make_uint2(*reinterpret_cast<uint32_t*>(&a),
                                         *reinterpret_cast<uint32_t*>(&b));
}

__global__ void w1_prep(const float* __restrict__ W1a, const float* __restrict__ W1b)
{
    int idx = blockIdx.x * blockDim.x + threadIdx.x;
    if (idx >= NAG * C_) return;
    int n = idx / C_, k = idx - n * C_;
    float v = (n < HM_) ? W1a[k * HM_ + n] : W1b[k * HM_ + (n - HM_)];
    __nv_bfloat16 h, l;
    bsplit(v, h, l);
    g_W1t_h[idx] = h;
    g_W1t_l[idx] = l;
}

// ============================================================
// Patch GEMM: feats = im2row(img) x Wp^T, fp16 2-pass (Ah,Al x Bh)
// grid (98, 3), 256 thr, 60KB smem, occ 2, K=3072 (96 chunks)
// ============================================================
__global__ void __launch_bounds__(256, 2)
patch_mma_kernel(const float* __restrict__ img, const float* __restrict__ bp)
{
    extern __shared__ __align__(128) char smem[];
    const uint32_t sb = smem_to_u32(smem);
    const int tid = threadIdx.x, lane = tid & 31, w = tid >> 5;
    const int wm = w >> 2, wn = w & 3;
    const int bm = blockIdx.x * 128, bn = blockIdx.y * 128;

    const int lrow = tid >> 1, lhalf = tid & 1;
    const float* abase;
    {
        int p  = bm + lrow;
        int n  = p / 49;
        int s  = p - n * 49;
        int py = s / 7, px = s - py * 7;
        abase = img + (n * CIN * HWD + py * PATCH) * HWD + px * PATCH + lhalf * 16;
    }

    float acc[4][4][4];
#pragma unroll
    for (int mi = 0; mi < 4; mi++)
#pragma unroll
        for (int ni = 0; ni < 4; ni++)
#pragma unroll
            for (int t = 0; t < 4; t++) acc[mi][ni][t] = 0.f;

    float4 areg[4];

    auto ldA = [&](int c) {
        int k = c * 32, ci = k >> 10, rem = k & 1023, y = rem >> 5;
        const float4* src = (const float4*)(abase + ci * (HWD * HWD) + y * HWD);
        areg[0] = src[0]; areg[1] = src[1]; areg[2] = src[2]; areg[3] = src[3];
    };
    auto stA = [&](int st) {
        char* dh = smem + st * P_STAGE + OFF_AH + lrow * ROWB + lhalf * 32;
        float v[16] = {areg[0].x, areg[0].y, areg[0].z, areg[0].w,
                       areg[1].x, areg[1].y, areg[1].z, areg[1].w,
                       areg[2].x, areg[2].y, areg[2].z, areg[2].w,
                       areg[3].x, areg[3].y, areg[3].z, areg[3].w};
        uint32_t hp[8], lp[8];
#pragma unroll
        for (int t = 0; t < 8; t++)
            hsplit2(v[2 * t], v[2 * t + 1], hp[t], lp[t]);
        *(uint4*)dh                 = make_uint4(hp[0], hp[1], hp[2], hp[3]);
        *(uint4*)(dh + 16)          = make_uint4(hp[4], hp[5], hp[6], hp[7]);
        *(uint4*)(dh + TILE_B)      = make_uint4(lp[0], lp[1], lp[2], lp[3]);
        *(uint4*)(dh + TILE_B + 16) = make_uint4(lp[4], lp[5], lp[6], lp[7]);
    };
    auto cpB = [&](int c, int st) {
        int kc = c * 32;
#pragma unroll
        for (int u = 0; u < 2; u++) {
            int idx = tid + u * 256;
            int row = idx >> 2, q = idx & 3;
            uint32_t dst = sb + st * P_STAGE + OFF_BH + row * ROWB + q * 16;
            long so = (long)(bn + row) * KCONV + kc + q * 8;
            cp16(dst, &g_Wph[so]);
        }
    };

    ldA(0);
    cpB(0, 0); CP_COMMIT();

    const int NC = KCONV / 32;
#pragma unroll 1
    for (int c = 0; c < NC; c++) {
        int s = c & 1;
        stA(s);
        bool more = (c + 1 < NC);
        if (more) { cpB(c + 1, s ^ 1); CP_COMMIT(); CP_WAIT1(); }
        else      { CP_WAIT0(); }
        __syncthreads();
        if (more) ldA(c + 1);
        {
            const uint32_t sbase = sb + s * P_STAGE;
#pragma unroll
            for (int step = 0; step < 2; step++) {
                const uint32_t co = (uint32_t)(step * 32 + (lane >> 4) * 16);
                uint32_t bfh[2][4];
#pragma unroll
                for (int nj = 0; nj < 2; nj++) {
                    uint32_t ro = (uint32_t)((wn * 32 + nj * 16 + (lane & 15)) * ROWB) + co;
                    ldm4(bfh[nj], sbase + OFF_BH + ro);
                }
#pragma unroll
                for (int mi = 0; mi < 4; mi++) {
                    uint32_t afh[4], afl[4];
                    uint32_t ro = (uint32_t)((wm * 64 + mi * 16 + (lane & 15)) * ROWB) + co;
                    ldm4(afh, sbase + OFF_AH + ro);
                    ldm4(afl, sbase + OFF_AL + ro);
#pragma unroll
                    for (int ni = 0; ni < 4; ni++) {
                        int nj = ni >> 1, o = ni & 1;
                        mma_f16(acc[mi][ni], afh, bfh[nj][o], bfh[nj][o + 2]);
                        mma_f16(acc[mi][ni], afl, bfh[nj][o], bfh[nj][o + 2]);
                    }
                }
            }
        }
        __syncthreads();
    }

    const int r  = lane >> 2;
    const int cc = (lane & 3) * 2;
#pragma unroll
    for (int mi = 0; mi < 4; mi++) {
#pragma unroll
        for (int ni = 0; ni < 4; ni++) {
            int m0  = bm + wm * 64 + mi * 16 + r;
            int col = bn + wn * 32 + ni * 8 + cc;
            float b0 = bp[col], b1 = bp[col + 1];
            {
                float x0 = acc[mi][ni][0] + b0, x1 = acc[mi][ni][1] + b1;
                __nv_bfloat16 h0, l0, h1, l1;
                bsplit(x0, h0, l0); bsplit(x1, h1, l1);
                *(uint32_t*)&g_feats_h[(long)m0 * C_ + col] = pk2(h0, h1);
                *(uint32_t*)&g_feats_l[(long)m0 * C_ + col] = pk2(l0, l1);
            }
            {
                float x0 = acc[mi][ni][2] + b0, x1 = acc[mi][ni][3] + b1;
                __nv_bfloat16 h0, l0, h1, l1;
                bsplit(x0, h0, l0); bsplit(x1, h1, l1);
                *(uint32_t*)&g_feats_h[(long)(m0 + 8) * C_ + col] = pk2(h0, h1);
                *(uint32_t*)&g_feats_l[(long)(m0 + 8) * C_ + col] = pk2(l0, l1);
            }
        }
    }
}

// ============================================================
// a|g GEMM: [12544 x 1024] = feats x W1t^T, bf16 3-pass, occ 2
// ============================================================
__global__ void __launch_bounds__(256, 2)
ag_mma_kernel()
{
    extern __shared__ __align__(128) char smem[];
    const uint32_t sb = smem_to_u32(smem);
    const int tid = threadIdx.x, lane = tid & 31, w = tid >> 5;
    const int wm = w >> 2, wn = w & 3;
    const int bm = blockIdx.x * 128, bn = blockIdx.y * 128;

    float acc[4][4][4];
#pragma unroll
    for (int mi = 0; mi < 4; mi++)
#pragma unroll
        for (int ni = 0; ni < 4; ni++)
#pragma unroll
            for (int t = 0; t < 4; t++) acc[mi][ni][t] = 0.f;

    auto cpAB = [&](int c, int st) {
        int kc = c * 32;
#pragma unroll
        for (int u = 0; u < 2; u++) {
            int idx = tid + u * 256;
            int row = idx >> 2, q = idx & 3;
            uint32_t base = sb + st * AG_STAGE + row * ROWB + q * 16;
            long ao = (long)(bm + row) * C_ + kc + q * 8;
            long bo = (long)(bn + row) * C_ + kc + q * 8;
            cp16(base + OFF_AH, &g_feats_h[ao]);
            cp16(base + OFF_AL, &g_feats_l[ao]);
            cp16(base + OFF_BH, &g_W1t_h[bo]);
            cp16(base + OFF_BL, &g_W1t_l[bo]);
        }
    };

    cpAB(0, 0); CP_COMMIT();

    const int NC = C_ / 32;
#pragma unroll 1
    for (int c = 0; c < NC; c++) {
        int s = c & 1;
        bool more = (c + 1 < NC);
        if (more) { cpAB(c + 1, s ^ 1); CP_COMMIT(); CP_WAIT1(); }
        else      { CP_WAIT0(); }
        __syncthreads();
        {
            const uint32_t sbase = sb + s * AG_STAGE;
#pragma unroll
            for (int step = 0; step < 2; step++) {
                const uint32_t co = (uint32_t)(step * 32 + (lane >> 4) * 16);
                uint32_t bfh[2][4], bfl[2][4];
#pragma unroll
                for (int nj = 0; nj < 2; nj++) {
                    uint32_t ro = (uint32_t)((wn * 32 + nj * 16 + (lane & 15)) * ROWB) + co;
                    ldm4(bfh[nj], sbase + OFF_BH + ro);
                    ldm4(bfl[nj], sbase + OFF_BL + ro);
                }
#pragma unroll
                for (int mi = 0; mi < 4; mi++) {
                    uint32_t afh[4], afl[4];
                    uint32_t ro = (uint32_t)((wm * 64 + mi * 16 + (lane & 15)) * ROWB) + co;
                    ldm4(afh, sbase + OFF_AH + ro);
                    ldm4(afl, sbase + OFF_AL + ro);
#pragma unroll
                    for (int ni = 0; ni < 4; ni++) {
                        int nj = ni >> 1, o = ni & 1;
                        mma_bf16(acc[mi][ni], afh, bfh[nj][o], bfh[nj][o + 2]);
                        mma_bf16(acc[mi][ni], afh, bfl[nj][o], bfl[nj][o + 2]);
                        mma_bf16(acc[mi][ni], afl, bfh[nj][o], bfh[nj][o + 2]);
                    }
                }
            }
        }
        __syncthreads();
    }

    float* dst = (bn < HM_) ? g_a : g_g;
    const int nb = (bn < HM_) ? bn : bn - HM_;
    const int r  = lane >> 2;
    const int cc = (lane & 3) * 2;
#pragma unroll
    for (int mi = 0; mi < 4; mi++) {
#pragma unroll
        for (int ni = 0; ni < 4; ni++) {
            int m0  = bm + wm * 64 + mi * 16 + r;
            int col = nb + wn * 32 + ni * 8 + cc;
            *(float2*)&dst[(long)m0 * HM_ + col] =
                make_float2(acc[mi][ni][0], acc[mi][ni][1]);
            *(float2*)&dst[(long)(m0 + 8) * HM_ + col] =
                make_float2(acc[mi][ni][2], acc[mi][ni][3]);
        }
    }
}

// ============================================================
// mask kernel
// ============================================================
__global__ void mask_kernel(const float* __restrict__ pos, float* __restrict__ out)
{
    int e = blockIdx.x * blockDim.x + threadIdx.x;
    if (e >= NE) return;
    int b = e >> 6, i = (e >> 3) & 7, j = e & 7;
    float xi = pos[(b * N_ + i) * 3 + 0], yi = pos[(b * N_ + i) * 3 + 1];
    float xj = pos[(b * N_ + j) * 3 + 0], yj = pos[(b * N_ + j) * 3 + 1];
    float dx = xi - xj, dy = yi - yj;
    float d2 = __fadd_rn(__fmul_rn(dx, dx), __fmul_rn(dy, dy));
    float m = (d2 < 0.25f && i != j) ? 1.0f : 0.0f;
    g_mask[e] = m;
    out[NE * 7 + e] = m;
}

// ============================================================
// w2h kernel: warp-per-h-row
// ============================================================
__device__ __forceinline__ float head_w(int o, int k,
                                        const float* Wph, const float* Wpv,
                                        const float* Wr, const float* Wrv)
{
    if (k < 2) return Wph[o * 2 + k];
    if (k < 4) return Wpv[o * 2 + (k - 2)];
    if (k < 6) return Wr[o * 2 + (k - 4)];
    return Wrv[o];
}

__global__ void __launch_bounds__(256)
w2h_kernel(const float* __restrict__ W2, const float* __restrict__ b2,
           const float* __restrict__ Wph, const float* __restrict__ bph,
           const float* __restrict__ Wpv, const float* __restrict__ bpv,
           const float* __restrict__ Wr,  const float* __restrict__ br,
           const float* __restrict__ Wrv, const float* __restrict__ brv)
{
    __shared__ float sW[CO_][7];
    const int tid = threadIdx.x, lane = tid & 31, wid = tid >> 5;

    if (tid < CO_) {
#pragma unroll
        for (int k = 0; k < 7; k++)
            sW[tid][k] = head_w(tid, k, Wph, Wpv, Wr, Wrv);
    }
    __syncthreads();

    const int h = blockIdx.x * 8 + wid;
    float acc[7] = {0, 0, 0, 0, 0, 0, 0};
#pragma unroll
    for (int t = 0; t < 8; t++) {
        int o = lane + 32 * t;
        float w2 = W2[h * CO_ + o];
#pragma unroll
        for (int k = 0; k < 7; k++)
            acc[k] = fmaf(w2, sW[o][k], acc[k]);
    }
#pragma unroll
    for (int k = 0; k < 7; k++) {
#pragma unroll
        for (int off = 16; off; off >>= 1)
            acc[k] += __shfl_down_sync(0xffffffffu, acc[k], off);
    }
    if (lane == 0) {
#pragma unroll
        for (int k = 0; k < 7; k++)
            g_W2h[h * 7 + k] = acc[k] * (1.0f / 49.0f);
    }

    if (blockIdx.x == 0 && tid < 7) {
        float sum = 0.f;
        for (int o = 0; o < CO_; o++)
            sum = fmaf(b2[o], sW[o][tid], sum);
        float bb = (tid < 2) ? bph[tid] : (tid < 4) ? bpv[tid - 2]
                 : (tid < 6) ? br[tid - 4] : brv[0];
        g_bias7[tid] = sum + bb;
    }
}

// ============================================================
// edge kernel: per-(b, i-half) block, thread-per-h
// ============================================================
__global__ void __launch_bounds__(512, 1)
edge_b_kernel(const float* __restrict__ b1, float* __restrict__ out)
{
    __shared__ float red[16][28];
    __shared__ float sbias[7];

    const int blk = blockIdx.x;
    const int b   = blk >> 1;
    const int ih  = blk & 1;
    const int tid = threadIdx.x, lane = tid & 31, wid = tid >> 5;

    if (tid < 7) sbias[tid] = g_bias7[tid];

    const float base = b1[tid];
    const float* __restrict__ ap = g_a + ((long)(b * 8 + ih * 4) * 49) * HM_ + tid;
    const float* __restrict__ gp = g_g + ((long)(b * 8) * 49) * HM_ + tid;

    float acc[32];
#pragma unroll
    for (int p = 0; p < 32; p++) acc[p] = 0.f;

#pragma unroll 1
    for (int s = 0; s < 49; s++) {
        const int so = s * HM_;
        float av[4], gv[8];
#pragma unroll
        for (int i = 0; i < 4; i++)
            av[i] = ap[i * (49 * HM_) + so] + base;
#pragma unroll
        for (int j = 0; j < 8; j++)
            gv[j] = gp[j * (49 * HM_) + so];
#pragma unroll
        for (int i = 0; i < 4; i++)
#pragma unroll
            for (int j = 0; j < 8; j++)
                acc[i * 8 + j] += fmaxf(av[i] + gv[j], 0.f);
    }

    float wv[7];
#pragma unroll
    for (int k = 0; k < 7; k++) wv[k] = g_W2h[tid * 7 + k];

    __syncthreads();

#pragma unroll 1
    for (int p0 = 0; p0 < 32; p0 += 4) {
        float pr[28];
#pragma unroll
        for (int q = 0; q < 4; q++)
#pragma unroll
            for (int k = 0; k < 7; k++)
                pr[q * 7 + k] = acc[p0 + q] * wv[k];
#pragma unroll
        for (int t = 0; t < 28; t++) {
#pragma unroll
            for (int off = 16; off; off >>= 1)
                pr[t] += __shfl_down_sync(0xffffffffu, pr[t], off);
        }
        if (lane == 0) {
#pragma unroll
            for (int t = 0; t < 28; t++) red[wid][t] = pr[t];
        }
        __syncthreads();
        if (tid < 28) {
            float v = 0.f;
#pragma unroll
            for (int ww = 0; ww < 16; ww++) v += red[ww][tid];
            int q = tid / 7, k = tid - 7 * q;
            int p = p0 + q;
            int i = ih * 4 + (p >> 3), j = p & 7;
            int e = b * 64 + i * 8 + j;
            float mf = g_mask[e];
            out[e * 7 + k] = (mf != 0.f) ? (v + sbias[k]) : 0.f;
        }
        __syncthreads();
    }
}

// ============================================================
// zero-fill node_preds section
// ============================================================
__global__ void zero_kernel(float* __restrict__ out, int n0, int n1)
{
    int idx = n0 + blockIdx.x * blockDim.x + threadIdx.x;
    if (idx < n1) out[idx] = 0.0f;
}

// ============================================================
extern "C" void kernel_launch(void* const* d_in, const int* in_sizes, int n_in,
                              void* d_out, int out_size)
{
    const float* img    = (const float*)d_in[0];
    const float* pos    = (const float*)d_in[1];
    /* d_in[2] = rot, unused */
    const float* Wpatch = (const float*)d_in[3];
    const float* bpatch = (const float*)d_in[4];
    const float* W1a    = (const float*)d_in[5];
    const float* W1b    = (const float*)d_in[6];
    const float* b1     = (const float*)d_in[7];
    const float* W2     = (const float*)d_in[8];
    const float* b2     = (const float*)d_in[9];
    const float* Wp     = (const float*)d_in[10];
    const float* bp     = (const float*)d_in[11];
    const float* Wpv    = (const float*)d_in[12];
    const float* bpv    = (const float*)d_in[13];
    const float* Wr     = (const float*)d_in[14];
    const float* br     = (const float*)d_in[15];
    const float* Wrv    = (const float*)d_in[16];
    const float* brv    = (const float*)d_in[17];
    float* out = (float*)d_out;

    cudaFuncSetAttribute(patch_mma_kernel,
                         cudaFuncAttributeMaxDynamicSharedMemorySize, P_SMEM);
    cudaFuncSetAttribute(ag_mma_kernel,
                         cudaFuncAttributeMaxDynamicSharedMemorySize, AG_SMEM);

    // independent prep
    wp_prep<<<(C_ * KCONV / 4 + 255) / 256, 256>>>(Wpatch);
    w1_prep<<<(NAG * C_ + 255) / 256, 256>>>(W1a, W1b);
    mask_kernel<<<(NE + 255) / 256, 256>>>(pos, out);
    w2h_kernel<<<64, 256>>>(W2, b2, Wp, bp, Wpv, bpv, Wr, br, Wrv, brv);
    // patch embedding GEMM (HMMA fp16 2-pass)
    patch_mma_kernel<<<dim3(NP / 128, C_ / 128), 256, P_SMEM>>>(img, bpatch);
    // a|g GEMM (HMMA bf16 3-pass)
    ag_mma_kernel<<<dim3(NP / 128, NAG / 128), 256, AG_SMEM>>>();
    // fused edge MLP + heads
    edge_b_kernel<<<64, 512>>>(b1, out);
    // node_preds zeros
    int n0 = NE * 7 + NE;
    int cnt = out_size - n0;
    if (cnt > 0)
        zero_kernel<<<(cnt + 255) / 256, 256>>>(out, n0, out_size);
}

// round 8
// speedup vs baseline: 8.8841x; 1.1882x over previous
#include <cuda_runtime.h>
#include <cuda_bf16.h>
#include <cuda_fp16.h>
#include <cstdint>

#define B_    32
#define N_    8
#define CIN   3
#define HWD   224
#define PATCH 32
#define S_    49
#define C_    384
#define HM_   512
#define CO_   256
#define NP    12544
#define KCONV 3072
#define NE    2048
#define NAG   1024
#define NIMG  (B_*N_*CIN*HWD*HWD)   /* 38,535,168 */

// ---- scratch (static device globals; no allocation) ----
__device__ __align__(16) __half g_img_h[NIMG];          // fp16 image
__device__ __align__(16) __half g_Wph[C_ * KCONV];      // fp16 Wp
__device__ __align__(16) __half g_W1t_h[NAG * C_];      // fp16 W1^T (a|b fused)
__device__ __align__(16) __half g_feats_h[NP * C_];     // feats hi
__device__ __align__(16) __half g_feats_l[NP * C_];     // feats lo residual
__device__ float g_a[NP * HM_];
__device__ float g_g[NP * HM_];
__device__ float g_mask[NE];
__device__ float g_W2h[HM_ * 7];
__device__ float g_bias7[7];

// ---- helpers ----
__device__ __forceinline__ uint32_t smem_to_u32(const void* p) {
    uint32_t a;
    asm("{ .reg .u64 t; cvta.to.shared.u64 t, %1; cvt.u32.u64 %0, t; }" : "=r"(a) : "l"(p));
    return a;
}
__device__ __forceinline__ void cp16(uint32_t dst, const void* src) {
    asm volatile("cp.async.cg.shared.global [%0], [%1], 16;" :: "r"(dst), "l"(src));
}
#define CP_COMMIT() asm volatile("cp.async.commit_group;" ::: "memory")
#define CP_WAIT1()  asm volatile("cp.async.wait_group 1;" ::: "memory")
#define CP_WAIT0()  asm volatile("cp.async.wait_group 0;" ::: "memory")

__device__ __forceinline__ void ldm4(uint32_t* r, uint32_t addr) {
    asm volatile("ldmatrix.sync.aligned.m8n8.x4.shared.b16 {%0,%1,%2,%3}, [%4];"
                 : "=r"(r[0]), "=r"(r[1]), "=r"(r[2]), "=r"(r[3]) : "r"(addr));
}
__device__ __forceinline__ void mma_f16(float* c, const uint32_t* a,
                                        uint32_t b0, uint32_t b1) {
    asm volatile(
        "mma.sync.aligned.m16n8k16.row.col.f32.f16.f16.f32 "
        "{%0,%1,%2,%3}, {%4,%5,%6,%7}, {%8,%9}, {%0,%1,%2,%3};"
        : "+f"(c[0]), "+f"(c[1]), "+f"(c[2]), "+f"(c[3])
        : "r"(a[0]), "r"(a[1]), "r"(a[2]), "r"(a[3]), "r"(b0), "r"(b1));
}
__device__ __forceinline__ void hsplit2(float x, float y, uint32_t& hp, uint32_t& lp) {
    __half hx = __float2half_rn(x), hy = __float2half_rn(y);
    __half lx = __float2half_rn(x - __half2float(hx));
    __half ly = __float2half_rn(y - __half2float(hy));
    __half2 h(hx, hy), l(lx, ly);
    hp = *reinterpret_cast<uint32_t*>(&h);
    lp = *reinterpret_cast<uint32_t*>(&l);
}

// smem rows: 32 fp16 (64B) padded to 80B (conflict-free mod 128)
#define ROWB    80
#define TILE_B  (128 * ROWB)            /* 10240 */
// patch (1-pass fp16): A + B = 2 tiles/stage
#define P_STAGE  (2 * TILE_B)           /* 20480 */
#define P_SMEM   (2 * P_STAGE)          /* 40960 */
#define POFF_A   0
#define POFF_B   TILE_B
// ag (2-pass fp16): Ah + Al + Bh = 3 tiles/stage
#define AG_STAGE (3 * TILE_B)           /* 30720 */
#define AG_SMEM  (2 * AG_STAGE)         /* 61440 */
#define OFF_AH   0
#define OFF_AL   TILE_B
#define OFF_BH   (2 * TILE_B)

// ============================================================
// Prep kernels
// ============================================================
__global__ void img_prep(const float* __restrict__ img)
{
    long i8 = ((long)blockIdx.x * blockDim.x + threadIdx.x) * 8;
    if (i8 >= NIMG) return;
    float4 v0 = *(const float4*)&img[i8];
    float4 v1 = *(const float4*)&img[i8 + 4];
    __half2 a = __floats2half2_rn(v0.x, v0.y);
    __half2 b = __floats2half2_rn(v0.z, v0.w);
    __half2 c = __floats2half2_rn(v1.x, v1.y);
    __half2 d = __floats2half2_rn(v1.z, v1.w);
    *(uint4*)&g_img_h[i8] = make_uint4(*reinterpret_cast<uint32_t*>(&a),
                                       *reinterpret_cast<uint32_t*>(&b),
                                       *reinterpret_cast<uint32_t*>(&c),
                                       *reinterpret_cast<uint32_t*>(&d));
}

__global__ void wp_prep(const float* __restrict__ Wp)
{
    int i4 = blockIdx.x * blockDim.x + threadIdx.x;
    if (i4 >= C_ * KCONV / 4) return;
    float4 v = *(const float4*)&Wp[i4 * 4];
    __half2 a = __floats2half2_rn(v.x, v.y);
    __half2 b = __floats2half2_rn(v.z, v.w);
    *(uint2*)&g_Wph[i4 * 4] = make_uint2(*reinterpret_cast<uint32_t*>(&a),
                                         *reinterpret_cast<uint32_t*>(&b));
}

__global__ void w1_prep(const float* __restrict__ W1a, const float* __restrict__ W1b)
{
    int idx = blockIdx.x * blockDim.x + threadIdx.x;
    if (idx >= NAG * C_) return;
    int n = idx / C_, k = idx - n * C_;
    float v = (n < HM_) ? W1a[k * HM_ + n] : W1b[k * HM_ + (n - HM_)];
    g_W1t_h[idx] = __float2half_rn(v);
}

// ============================================================
// Patch GEMM: feats = im2row(img_h) x Wp^T, fp16 1-pass
// grid (98, 3), 256 thr, 40KB smem, K=3072 (96 chunks of 32)
// ============================================================
__global__ void __launch_bounds__(256, 2)
patch_mma_kernel(const float* __restrict__ bp)
{
    extern __shared__ __align__(128) char smem[];
    const uint32_t sb = smem_to_u32(smem);
    const int tid = threadIdx.x, lane = tid & 31, w = tid >> 5;
    const int wm = w >> 2, wn = w & 3;
    const int bm = blockIdx.x * 128, bn = blockIdx.y * 128;

    // loaders: row = tid>>1, seg = tid&1 (16 fp16 = 32B each)
    const int lrow = tid >> 1, lseg = tid & 1;
    int abase;
    {
        int p  = bm + lrow;
        int n  = p / 49;
        int s  = p - n * 49;
        int py = s / 7, px = s - py * 7;
        abase = (n * CIN * HWD + py * PATCH) * HWD + px * PATCH + lseg * 16;
    }
    const long brow = (long)(bn + lrow) * KCONV + lseg * 16;

    float acc[4][4][4];
#pragma unroll
    for (int mi = 0; mi < 4; mi++)
#pragma unroll
        for (int ni = 0; ni < 4; ni++)
#pragma unroll
            for (int t = 0; t < 4; t++) acc[mi][ni][t] = 0.f;

    auto cpAB = [&](int c, int st) {
        int k  = c * 32;
        int ci = k >> 10, rem = k & 1023, y = rem >> 5;
        const __half* asrc = g_img_h + abase + ci * (HWD * HWD) + y * HWD;
        uint32_t ad = sb + st * P_STAGE + POFF_A + lrow * ROWB + lseg * 32;
        cp16(ad, asrc);
        cp16(ad + 16, asrc + 8);
        const __half* bsrc = g_Wph + brow + k;
        uint32_t bd = sb + st * P_STAGE + POFF_B + lrow * ROWB + lseg * 32;
        cp16(bd, bsrc);
        cp16(bd + 16, bsrc + 8);
    };

    cpAB(0, 0); CP_COMMIT();

    const int NC = KCONV / 32;
#pragma unroll 1
    for (int c = 0; c < NC; c++) {
        int s = c & 1;
        bool more = (c + 1 < NC);
        if (more) { cpAB(c + 1, s ^ 1); CP_COMMIT(); CP_WAIT1(); }
        else      { CP_WAIT0(); }
        __syncthreads();
        {
            const uint32_t sbase = sb + s * P_STAGE;
#pragma unroll
            for (int step = 0; step < 2; step++) {
                const uint32_t co = (uint32_t)(step * 32 + (lane >> 4) * 16);
                uint32_t bf[2][4];
#pragma unroll
                for (int nj = 0; nj < 2; nj++) {
                    uint32_t ro = (uint32_t)((wn * 32 + nj * 16 + (lane & 15)) * ROWB) + co;
                    ldm4(bf[nj], sbase + POFF_B + ro);
                }
#pragma unroll
                for (int mi = 0; mi < 4; mi++) {
                    uint32_t af[4];
                    uint32_t ro = (uint32_t)((wm * 64 + mi * 16 + (lane & 15)) * ROWB) + co;
                    ldm4(af, sbase + POFF_A + ro);
#pragma unroll
                    for (int ni = 0; ni < 4; ni++) {
                        int nj = ni >> 1, o = ni & 1;
                        mma_f16(acc[mi][ni], af, bf[nj][o], bf[nj][o + 2]);
                    }
                }
            }
        }
        __syncthreads();
    }

    const int r  = lane >> 2;
    const int cc = (lane & 3) * 2;
#pragma unroll
    for (int mi = 0; mi < 4; mi++) {
#pragma unroll
        for (int ni = 0; ni < 4; ni++) {
            int m0  = bm + wm * 64 + mi * 16 + r;
            int col = bn + wn * 32 + ni * 8 + cc;
            float b0 = bp[col], b1 = bp[col + 1];
            uint32_t hp, lp;
            hsplit2(acc[mi][ni][0] + b0, acc[mi][ni][1] + b1, hp, lp);
            *(uint32_t*)&g_feats_h[(long)m0 * C_ + col] = hp;
            *(uint32_t*)&g_feats_l[(long)m0 * C_ + col] = lp;
            hsplit2(acc[mi][ni][2] + b0, acc[mi][ni][3] + b1, hp, lp);
            *(uint32_t*)&g_feats_h[(long)(m0 + 8) * C_ + col] = hp;
            *(uint32_t*)&g_feats_l[(long)(m0 + 8) * C_ + col] = lp;
        }
    }
}

// ============================================================
// a|g GEMM: [12544 x 1024] = feats x W1t^T, fp16 2-pass (Ah,Al x Bh)
// grid (98, 8), K=384 (12 chunks of 32)
// ============================================================
__global__ void __launch_bounds__(256, 2)
ag_mma_kernel()
{
    extern __shared__ __align__(128) char smem[];
    const uint32_t sb = smem_to_u32(smem);
    const int tid = threadIdx.x, lane = tid & 31, w = tid >> 5;
    const int wm = w >> 2, wn = w & 3;
    const int bm = blockIdx.x * 128, bn = blockIdx.y * 128;

    float acc[4][4][4];
#pragma unroll
    for (int mi = 0; mi < 4; mi++)
#pragma unroll
        for (int ni = 0; ni < 4; ni++)
#pragma unroll
            for (int t = 0; t < 4; t++) acc[mi][ni][t] = 0.f;

    auto cpAB = [&](int c, int st) {
        int kc = c * 32;
#pragma unroll
        for (int u = 0; u < 2; u++) {
            int idx = tid + u * 256;
            int row = idx >> 2, q = idx & 3;
            uint32_t base = sb + st * AG_STAGE + row * ROWB + q * 16;
            long ao = (long)(bm + row) * C_ + kc + q * 8;
            long bo = (long)(bn + row) * C_ + kc + q * 8;
            cp16(base + OFF_AH, &g_feats_h[ao]);
            cp16(base + OFF_AL, &g_feats_l[ao]);
            cp16(base + OFF_BH, &g_W1t_h[bo]);
        }
    };

    cpAB(0, 0); CP_COMMIT();

    const int NC = C_ / 32;
#pragma unroll 1
    for (int c = 0; c < NC; c++) {
        int s = c & 1;
        bool more = (c + 1 < NC);
        if (more) { cpAB(c + 1, s ^ 1); CP_COMMIT(); CP_WAIT1(); }
        else      { CP_WAIT0(); }
        __syncthreads();
        {
            const uint32_t sbase = sb + s * AG_STAGE;
#pragma unroll
            for (int step = 0; step < 2; step++) {
                const uint32_t co = (uint32_t)(step * 32 + (lane >> 4) * 16);
                uint32_t bf[2][4];
#pragma unroll
                for (int nj = 0; nj < 2; nj++) {
                    uint32_t ro = (uint32_t)((wn * 32 + nj * 16 + (lane & 15)) * ROWB) + co;
                    ldm4(bf[nj], sbase + OFF_BH + ro);
                }
#pragma unroll
                for (int mi = 0; mi < 4; mi++) {
                    uint32_t afh[4], afl[4];
                    uint32_t ro = (uint32_t)((wm * 64 + mi * 16 + (lane & 15)) * ROWB) + co;
                    ldm4(afh, sbase + OFF_AH + ro);
                    ldm4(afl, sbase + OFF_AL + ro);
#pragma unroll
                    for (int ni = 0; ni < 4; ni++) {
                        int nj = ni >> 1, o = ni & 1;
                        mma_f16(acc[mi][ni], afh, bf[nj][o], bf[nj][o + 2]);
                        mma_f16(acc[mi][ni], afl, bf[nj][o], bf[nj][o + 2]);
                    }
                }
            }
        }
        __syncthreads();
    }

    float* dst = (bn < HM_) ? g_a : g_g;
    const int nb = (bn < HM_) ? bn : bn - HM_;
    const int r  = lane >> 2;
    const int cc = (lane & 3) * 2;
#pragma unroll
    for (int mi = 0; mi < 4; mi++) {
#pragma unroll
        for (int ni = 0; ni < 4; ni++) {
            int m0  = bm + wm * 64 + mi * 16 + r;
            int col = nb + wn * 32 + ni * 8 + cc;
            *(float2*)&dst[(long)m0 * HM_ + col] =
                make_float2(acc[mi][ni][0], acc[mi][ni][1]);
            *(float2*)&dst[(long)(m0 + 8) * HM_ + col] =
                make_float2(acc[mi][ni][2], acc[mi][ni][3]);
        }
    }
}

// ============================================================
// mask kernel
// ============================================================
__global__ void mask_kernel(const float* __restrict__ pos, float* __restrict__ out)
{
    int e = blockIdx.x * blockDim.x + threadIdx.x;
    if (e >= NE) return;
    int b = e >> 6, i = (e >> 3) & 7, j = e & 7;
    float xi = pos[(b * N_ + i) * 3 + 0], yi = pos[(b * N_ + i) * 3 + 1];
    float xj = pos[(b * N_ + j) * 3 + 0], yj = pos[(b * N_ + j) * 3 + 1];
    float dx = xi - xj, dy = yi - yj;
    float d2 = __fadd_rn(__fmul_rn(dx, dx), __fmul_rn(dy, dy));
    float m = (d2 < 0.25f && i != j) ? 1.0f : 0.0f;
    g_mask[e] = m;
    out[NE * 7 + e] = m;
}

// ============================================================
// w2h kernel: warp-per-h-row
// ============================================================
__device__ __forceinline__ float head_w(int o, int k,
                                        const float* Wph, const float* Wpv,
                                        const float* Wr, const float* Wrv)
{
    if (k < 2) return Wph[o * 2 + k];
    if (k < 4) return Wpv[o * 2 + (k - 2)];
    if (k < 6) return Wr[o * 2 + (k - 4)];
    return Wrv[o];
}

__global__ void __launch_bounds__(256)
w2h_kernel(const float* __restrict__ W2, const float* __restrict__ b2,
           const float* __restrict__ Wph, const float* __restrict__ bph,
           const float* __restrict__ Wpv, const float* __restrict__ bpv,
           const float* __restrict__ Wr,  const float* __restrict__ br,
           const float* __restrict__ Wrv, const float* __restrict__ brv)
{
    __shared__ float sW[CO_][7];
    const int tid = threadIdx.x, lane = tid & 31, wid = tid >> 5;

    if (tid < CO_) {
#pragma unroll
        for (int k = 0; k < 7; k++)
            sW[tid][k] = head_w(tid, k, Wph, Wpv, Wr, Wrv);
    }
    __syncthreads();

    const int h = blockIdx.x * 8 + wid;
    float acc[7] = {0, 0, 0, 0, 0, 0, 0};
#pragma unroll
    for (int t = 0; t < 8; t++) {
        int o = lane + 32 * t;
        float w2 = W2[h * CO_ + o];
#pragma unroll
        for (int k = 0; k < 7; k++)
            acc[k] = fmaf(w2, sW[o][k], acc[k]);
    }
#pragma unroll
    for (int k = 0; k < 7; k++) {
#pragma unroll
        for (int off = 16; off; off >>= 1)
            acc[k] += __shfl_down_sync(0xffffffffu, acc[k], off);
    }
    if (lane == 0) {
#pragma unroll
        for (int k = 0; k < 7; k++)
            g_W2h[h * 7 + k] = acc[k] * (1.0f / 49.0f);
    }

    if (blockIdx.x == 0 && tid < 7) {
        float sum = 0.f;
        for (int o = 0; o < CO_; o++)
            sum = fmaf(b2[o], sW[o][tid], sum);
        float bb = (tid < 2) ? bph[tid] : (tid < 4) ? bpv[tid - 2]
                 : (tid < 6) ? br[tid - 4] : brv[0];
        g_bias7[tid] = sum + bb;
    }
}

// ============================================================
// edge kernel: per-(b, i-half) block, thread-per-h
// ============================================================
__global__ void __launch_bounds__(512, 1)
edge_b_kernel(const float* __restrict__ b1, float* __restrict__ out)
{
    __shared__ float red[16][28];
    __shared__ float sbias[7];

    const int blk = blockIdx.x;
    const int b   = blk >> 1;
    const int ih  = blk & 1;
    const int tid = threadIdx.x, lane = tid & 31, wid = tid >> 5;

    if (tid < 7) sbias[tid] = g_bias7[tid];

    const float base = b1[tid];
    const float* __restrict__ ap = g_a + ((long)(b * 8 + ih * 4) * 49) * HM_ + tid;
    const float* __restrict__ gp = g_g + ((long)(b * 8) * 49) * HM_ + tid;

    float acc[32];
#pragma unroll
    for (int p = 0; p < 32; p++) acc[p] = 0.f;

#pragma unroll 1
    for (int s = 0; s < 49; s++) {
        const int so = s * HM_;
        float av[4], gv[8];
#pragma unroll
        for (int i = 0; i < 4; i++)
            av[i] = ap[i * (49 * HM_) + so] + base;
#pragma unroll
        for (int j = 0; j < 8; j++)
            gv[j] = gp[j * (49 * HM_) + so];
#pragma unroll
        for (int i = 0; i < 4; i++)
#pragma unroll
            for (int j = 0; j < 8; j++)
                acc[i * 8 + j] += fmaxf(av[i] + gv[j], 0.f);
    }

    float wv[7];
#pragma unroll
    for (int k = 0; k < 7; k++) wv[k] = g_W2h[tid * 7 + k];

    __syncthreads();

#pragma unroll 1
    for (int p0 = 0; p0 < 32; p0 += 4) {
        float pr[28];
#pragma unroll
        for (int q = 0; q < 4; q++)
#pragma unroll
            for (int k = 0; k < 7; k++)
                pr[q * 7 + k] = acc[p0 + q] * wv[k];
#pragma unroll
        for (int t = 0; t < 28; t++) {
#pragma unroll
            for (int off = 16; off; off >>= 1)
                pr[t] += __shfl_down_sync(0xffffffffu, pr[t], off);
        }
        if (lane == 0) {
#pragma unroll
            for (int t = 0; t < 28; t++) red[wid][t] = pr[t];
        }
        __syncthreads();
        if (tid < 28) {
            float v = 0.f;
#pragma unroll
            for (int ww = 0; ww < 16; ww++) v += red[ww][tid];
            int q = tid / 7, k = tid - 7 * q;
            int p = p0 + q;
            int i = ih * 4 + (p >> 3), j = p & 7;
            int e = b * 64 + i * 8 + j;
            float mf = g_mask[e];
            out[e * 7 + k] = (mf != 0.f) ? (v + sbias[k]) : 0.f;
        }
        __syncthreads();
    }
}

// ============================================================
// zero-fill node_preds section
// ============================================================
__global__ void zero_kernel(float* __restrict__ out, int n0, int n1)
{
    int idx = n0 + blockIdx.x * blockDim.x + threadIdx.x;
    if (idx < n1) out[idx] = 0.0f;
}

// ============================================================
extern "C" void kernel_launch(void* const* d_in, const int* in_sizes, int n_in,
                              void* d_out, int out_size)
{
    const float* img    = (const float*)d_in[0];
    const float* pos    = (const float*)d_in[1];
    /* d_in[2] = rot, unused */
    const float* Wpatch = (const float*)d_in[3];
    const float* bpatch = (const float*)d_in[4];
    const float* W1a    = (const float*)d_in[5];
    const float* W1b    = (const float*)d_in[6];
    const float* b1     = (const float*)d_in[7];
    const float* W2     = (const float*)d_in[8];
    const float* b2     = (const float*)d_in[9];
    const float* Wp     = (const float*)d_in[10];
    const float* bp     = (const float*)d_in[11];
    const float* Wpv    = (const float*)d_in[12];
    const float* bpv    = (const float*)d_in[13];
    const float* Wr     = (const float*)d_in[14];
    const float* br     = (const float*)d_in[15];
    const float* Wrv    = (const float*)d_in[16];
    const float* brv    = (const float*)d_in[17];
    float* out = (float*)d_out;

    cudaFuncSetAttribute(patch_mma_kernel,
                         cudaFuncAttributeMaxDynamicSharedMemorySize, P_SMEM);
    cudaFuncSetAttribute(ag_mma_kernel,
                         cudaFuncAttributeMaxDynamicSharedMemorySize, AG_SMEM);

    // independent prep
    img_prep<<<NIMG / (256 * 8), 256>>>(img);
    wp_prep<<<(C_ * KCONV / 4 + 255) / 256, 256>>>(Wpatch);
    w1_prep<<<(NAG * C_ + 255) / 256, 256>>>(W1a, W1b);
    mask_kernel<<<(NE + 255) / 256, 256>>>(pos, out);
    w2h_kernel<<<64, 256>>>(W2, b2, Wp, bp, Wpv, bpv, Wr, br, Wrv, brv);
    // patch embedding GEMM (fp16 1-pass)
    patch_mma_kernel<<<dim3(NP / 128, C_ / 128), 256, P_SMEM>>>(bpatch);
    // a|g GEMM (fp16 2-pass)
    ag_mma_kernel<<<dim3(NP / 128, NAG / 128), 256, AG_SMEM>>>();
    // fused edge MLP + heads
    edge_b_kernel<<<64, 512>>>(b1, out);
    // node_preds zeros
    int n0 = NE * 7 + NE;
    int cnt = out_size - n0;
    if (cnt > 0)
        zero_kernel<<<(cnt + 255) / 256, 256>>>(out, n0, out_size);
}